// round 1
// baseline (speedup 1.0000x reference)
#include <cuda_runtime.h>
#include <cstdint>

#define THREADS 256
#define LD 64   // row stride (floats) of all SMEM activation buffers

// SMEM working set per CTA (2 batches, rows padded to 32 each -> 64 rows)
struct SM {
    float x[64 * LD];      // residual stream
    float h[64 * LD];      // LN output / attention output
    float q[64 * LD];      // Q  (reused as FFN tmp)
    float k[64 * LD];      // K
    float v[64 * LD];      // V
    float w[56 * LD];      // staged weight block (56 x 64, cols 56..63 zero)
};

__device__ __forceinline__ float fast_tanh(float x) {
    float r;
    asm("tanh.approx.f32 %0, %1;" : "=f"(r) : "f"(x));
    return r;
}

__device__ __forceinline__ float gelu_t(float x) {
    // jax.nn.gelu approximate=True (tanh form)
    float t = fast_tanh(0.7978845608028654f * (x + 0.044715f * x * x * x));
    return 0.5f * x * (1.0f + t);
}

// Stage a 56x56 weight block (row stride ld in gmem) into sm->w [56][64], zero-padding cols 56..63
__device__ __forceinline__ void stage_w(float* __restrict__ dst, const float* __restrict__ src,
                                        int ld, int tid) {
    #pragma unroll
    for (int i = tid; i < 56 * LD; i += THREADS) {
        int r = i >> 6, c = i & 63;
        dst[i] = (c < 56) ? __ldg(src + r * ld + c) : 0.0f;
    }
}

// LayerNorm over 56 cols; 4 threads per row (64 rows x 4 = 256 threads)
__device__ __forceinline__ void layer_norm(const float* __restrict__ X, float* __restrict__ H,
                                           const float* __restrict__ g, const float* __restrict__ b,
                                           int tid) {
    int row = tid >> 2, part = tid & 3;
    const float* xr = X + row * LD + part * 14;
    float s = 0.f, ss = 0.f;
    #pragma unroll
    for (int j = 0; j < 14; j++) { float v = xr[j]; s += v; ss += v * v; }
    s  += __shfl_xor_sync(0xffffffffu, s, 1);
    ss += __shfl_xor_sync(0xffffffffu, ss, 1);
    s  += __shfl_xor_sync(0xffffffffu, s, 2);
    ss += __shfl_xor_sync(0xffffffffu, ss, 2);
    float m   = s * (1.0f / 56.0f);
    float var = ss * (1.0f / 56.0f) - m * m;
    float rs  = rsqrtf(var + 1e-5f);
    float* hr = H + row * LD + part * 14;
    #pragma unroll
    for (int j = 0; j < 14; j++) {
        int col = part * 14 + j;
        hr[j] = (xr[j] - m) * rs * __ldg(g + col) + __ldg(b + col);
    }
}

// C[64][64] (op)= A[64][0..55] @ W[56][64];  thread tile 4x4, 16x16 thread grid
// MODE 0: store   1: C += acc   2: C = gelu(acc + bias[col])   3: C += acc + bias[col]
template <int MODE>
__device__ __forceinline__ void gemm_tile(const float* __restrict__ A, const float* __restrict__ W,
                                          float* __restrict__ C, const float* __restrict__ bias,
                                          int tid) {
    const int tm = tid >> 4;      // 0..15 -> rows tm*4..tm*4+3
    const int tn = tid & 15;      // 0..15 -> cols tn*4..tn*4+3
    const float* Ab = A + tm * 4 * LD;
    const float* Wb = W + tn * 4;
    float acc[4][4];
    #pragma unroll
    for (int r = 0; r < 4; r++)
        #pragma unroll
        for (int c = 0; c < 4; c++) acc[r][c] = 0.f;

    #pragma unroll 2
    for (int k = 0; k < 56; k += 4) {
        float4 a0 = *(const float4*)(Ab + 0 * LD + k);
        float4 a1 = *(const float4*)(Ab + 1 * LD + k);
        float4 a2 = *(const float4*)(Ab + 2 * LD + k);
        float4 a3 = *(const float4*)(Ab + 3 * LD + k);
        float4 w0 = *(const float4*)(Wb + (k + 0) * LD);
        float4 w1 = *(const float4*)(Wb + (k + 1) * LD);
        float4 w2 = *(const float4*)(Wb + (k + 2) * LD);
        float4 w3 = *(const float4*)(Wb + (k + 3) * LD);
        float av[4][4] = {{a0.x, a0.y, a0.z, a0.w}, {a1.x, a1.y, a1.z, a1.w},
                          {a2.x, a2.y, a2.z, a2.w}, {a3.x, a3.y, a3.z, a3.w}};
        float bv[4][4] = {{w0.x, w0.y, w0.z, w0.w}, {w1.x, w1.y, w1.z, w1.w},
                          {w2.x, w2.y, w2.z, w2.w}, {w3.x, w3.y, w3.z, w3.w}};
        #pragma unroll
        for (int kk = 0; kk < 4; kk++)
            #pragma unroll
            for (int r = 0; r < 4; r++) {
                acc[r][0] += av[r][kk] * bv[kk][0];
                acc[r][1] += av[r][kk] * bv[kk][1];
                acc[r][2] += av[r][kk] * bv[kk][2];
                acc[r][3] += av[r][kk] * bv[kk][3];
            }
    }

    #pragma unroll
    for (int r = 0; r < 4; r++) {
        float* Cr = C + (tm * 4 + r) * LD + tn * 4;
        #pragma unroll
        for (int c = 0; c < 4; c++) {
            float vacc = acc[r][c];
            if (MODE == 0) {
                Cr[c] = vacc;
            } else if (MODE == 1) {
                Cr[c] += vacc;
            } else if (MODE == 2) {
                int col = tn * 4 + c;
                float bb = (col < 56) ? __ldg(bias + col) : 0.f;
                Cr[c] = gelu_t(vacc + bb);
            } else {
                int col = tn * 4 + c;
                float bb = (col < 56) ? __ldg(bias + col) : 0.f;
                Cr[c] += vacc + bb;
            }
        }
    }
}

__global__ void __launch_bounds__(THREADS, 2)
nbody_kernel(const float* __restrict__ nodes, const float* __restrict__ edges,
             const float* __restrict__ mask,
             const float* __restrict__ W_in, const float* __restrict__ b_in,
             const float* __restrict__ W_gp, const float* __restrict__ b_gp,
             const float* __restrict__ Wq, const float* __restrict__ Wk,
             const float* __restrict__ Wv, const float* __restrict__ Wo,
             const float* __restrict__ ln1g, const float* __restrict__ ln1b,
             const float* __restrict__ ln2g, const float* __restrict__ ln2b,
             const float* __restrict__ W1, const float* __restrict__ b1,
             const float* __restrict__ W2, const float* __restrict__ b2,
             float* __restrict__ out, int Btot) {
    extern __shared__ float smem_raw[];
    SM* sm = reinterpret_cast<SM*>(smem_raw);
    const int tid = threadIdx.x;
    const int bx  = blockIdx.x;

    // ---- zero residual buffer (pad rows/cols must be finite) ----
    #pragma unroll
    for (int i = tid; i < 64 * LD; i += THREADS) sm->x[i] = 0.f;
    __syncthreads();

    // ---- embedding: mv_linear -> geometric product -> mv_linear ----
    if (tid < 50) {
        int g = tid / 25, s = tid % 25;
        long Bidx = (long)bx * 2 + g;
        if (Bidx < Btot) {
            const float* sp = (s < 5) ? nodes + (Bidx * 5 + s) * 24
                                      : edges + (Bidx * 20 + (s - 5)) * 24;
            float xin[24];
            #pragma unroll
            for (int i = 0; i < 24; i++) xin[i] = __ldg(sp + i);
            const int GR[8]  = {0, 1, 1, 1, 2, 2, 2, 3};
            const int POS[8] = {0, 1, 2, 4, 3, 5, 6, 7};
            float* xrow = sm->x + (g * 32 + s) * LD;
            #pragma unroll 1
            for (int n = 0; n < 7; n++) {
                float acc[8];
                #pragma unroll
                for (int i = 0; i < 8; i++) acc[i] = (i == 0) ? __ldg(b_gp + n) : 0.f;
                #pragma unroll 1
                for (int m = 0; m < 7; m++) {
                    float mv[8];
                    #pragma unroll
                    for (int i = 0; i < 8; i++) {
                        int gr = GR[i];
                        mv[i] = xin[i]      * __ldg(W_in + m * 12 + 0 + gr)
                              + xin[8 + i]  * __ldg(W_in + m * 12 + 4 + gr)
                              + xin[16 + i] * __ldg(W_in + m * 12 + 8 + gr);
                    }
                    mv[0] += __ldg(b_in + m);
                    float gp[8];
                    #pragma unroll
                    for (int j = 0; j < 8; j++) gp[j] = 0.f;
                    #pragma unroll
                    for (int a = 0; a < 8; a++) {
                        #pragma unroll
                        for (int bb = 0; bb < 8; bb++) {
                            int sc = 0;
                            #pragma unroll
                            for (int t = a >> 1; t; t >>= 1) sc += __popc(t & bb);
                            float sg = (sc & 1) ? -1.f : 1.f;
                            gp[POS[a ^ bb]] += sg * mv[POS[a]] * mv[POS[bb]];
                        }
                    }
                    #pragma unroll
                    for (int i = 0; i < 8; i++) {
                        int gr = GR[i];
                        acc[i] += mv[i] * __ldg(W_gp + n * 56 + m * 4 + gr)
                                + gp[i] * __ldg(W_gp + n * 56 + (m + 7) * 4 + gr);
                    }
                }
                #pragma unroll
                for (int i = 0; i < 8; i++) xrow[n * 8 + i] = acc[i];
            }
        }
    }
    __syncthreads();

    // ---- 4 transformer layers, fully in SMEM ----
    #pragma unroll 1
    for (int l = 0; l < 4; l++) {
        layer_norm(sm->x, sm->h, ln1g + l * 56, ln1b + l * 56, tid);
        __syncthreads();

        stage_w(sm->w, Wq + l * 3136, 56, tid); __syncthreads();
        gemm_tile<0>(sm->h, sm->w, sm->q, nullptr, tid); __syncthreads();
        stage_w(sm->w, Wk + l * 3136, 56, tid); __syncthreads();
        gemm_tile<0>(sm->h, sm->w, sm->k, nullptr, tid); __syncthreads();
        stage_w(sm->w, Wv + l * 3136, 56, tid); __syncthreads();
        gemm_tile<0>(sm->h, sm->w, sm->v, nullptr, tid); __syncthreads();

        // attention: item = (batch g, head hh, query s); writes o into sm->h
        #pragma unroll 1
        for (int it = tid; it < 400; it += THREADS) {
            int g  = it / 200;
            int r  = it % 200;
            int hh = r / 25;
            int s  = r % 25;
            long Bidx = (long)bx * 2 + g;
            int rq = (g * 32 + s) * LD + hh * 7;
            float qv[7];
            #pragma unroll
            for (int d = 0; d < 7; d++) qv[d] = sm->q[rq + d];
            const float* mrow = mask + (Bidx * 25 + s) * 25;
            float sc[25];
            float mx = -1e30f;
            #pragma unroll
            for (int ki = 0; ki < 25; ki++) {
                const float* kp = sm->k + (g * 32 + ki) * LD + hh * 7;
                float dot = 0.f;
                #pragma unroll
                for (int d = 0; d < 7; d++) dot += qv[d] * kp[d];
                float msk = (Bidx < Btot) ? __ldg(mrow + ki) : 0.f;
                sc[ki] = dot * 0.3779644730092272f + msk;  // 1/sqrt(7)
                mx = fmaxf(mx, sc[ki]);
            }
            float sum = 0.f;
            #pragma unroll
            for (int ki = 0; ki < 25; ki++) { float e = __expf(sc[ki] - mx); sc[ki] = e; sum += e; }
            float inv = 1.0f / sum;
            float o[7];
            #pragma unroll
            for (int d = 0; d < 7; d++) o[d] = 0.f;
            #pragma unroll
            for (int ki = 0; ki < 25; ki++) {
                const float* vp = sm->v + (g * 32 + ki) * LD + hh * 7;
                float p = sc[ki];
                #pragma unroll
                for (int d = 0; d < 7; d++) o[d] += p * vp[d];
            }
            #pragma unroll
            for (int d = 0; d < 7; d++) sm->h[rq + d] = o[d] * inv;
        }
        __syncthreads();

        stage_w(sm->w, Wo + l * 3136, 56, tid); __syncthreads();
        gemm_tile<1>(sm->h, sm->w, sm->x, nullptr, tid); __syncthreads();

        layer_norm(sm->x, sm->h, ln2g + l * 56, ln2b + l * 56, tid);
        __syncthreads();

        // FFN: x += gelu(h @ W1 + b1) @ W2 + b2, chunked 56 cols of Dff at a time
        #pragma unroll 1
        for (int c = 0; c < 4; c++) {
            stage_w(sm->w, W1 + l * 12544 + c * 56, 224, tid); __syncthreads();
            gemm_tile<2>(sm->h, sm->w, sm->q, b1 + l * 224 + c * 56, tid); __syncthreads();
            stage_w(sm->w, W2 + l * 12544 + c * 3136, 56, tid); __syncthreads();
            if (c == 3) gemm_tile<3>(sm->q, sm->w, sm->x, b2 + l * 56, tid);
            else        gemm_tile<1>(sm->q, sm->w, sm->x, nullptr, tid);
            __syncthreads();
        }
    }

    // ---- output: x[b, s<5, channel 1, :]  (D cols 8..15) ----
    if (tid < 80) {
        int g = tid / 40, r = tid % 40, s = r / 8, i = r % 8;
        long Bidx = (long)bx * 2 + g;
        if (Bidx < Btot) out[(Bidx * 5 + s) * 8 + i] = sm->x[(g * 32 + s) * LD + 8 + i];
    }
}

extern "C" void kernel_launch(void* const* d_in, const int* in_sizes, int n_in,
                              void* d_out, int out_size) {
    // inputs (setup_inputs order): nodes, edges, src_mask, [batch_size], W_in, b_in,
    // W_gp, b_gp, Wq, Wk, Wv, Wo, ln1_g, ln1_b, ln2_g, ln2_b, W1, b1, W2, b2
    int o = (n_in >= 20) ? 4 : 3;  // index of W_in (defensive: scalar batch_size may be dropped)
    const float* nodes = (const float*)d_in[0];
    const float* edges = (const float*)d_in[1];
    const float* mask  = (const float*)d_in[2];
    const float* W_in  = (const float*)d_in[o + 0];
    const float* b_in  = (const float*)d_in[o + 1];
    const float* W_gp  = (const float*)d_in[o + 2];
    const float* b_gp  = (const float*)d_in[o + 3];
    const float* Wq    = (const float*)d_in[o + 4];
    const float* Wk    = (const float*)d_in[o + 5];
    const float* Wv    = (const float*)d_in[o + 6];
    const float* Wo    = (const float*)d_in[o + 7];
    const float* ln1g  = (const float*)d_in[o + 8];
    const float* ln1b  = (const float*)d_in[o + 9];
    const float* ln2g  = (const float*)d_in[o + 10];
    const float* ln2b  = (const float*)d_in[o + 11];
    const float* W1    = (const float*)d_in[o + 12];
    const float* b1    = (const float*)d_in[o + 13];
    const float* W2    = (const float*)d_in[o + 14];
    const float* b2    = (const float*)d_in[o + 15];
    float* outp = (float*)d_out;

    int B = in_sizes[0] / 120;      // nodes: (B*5, 3, 8)
    int grid = (B + 1) / 2;         // 2 batches per CTA
    size_t shmem = sizeof(SM);      // 96256 bytes

    cudaFuncSetAttribute(nbody_kernel, cudaFuncAttributeMaxDynamicSharedMemorySize, (int)shmem);
    nbody_kernel<<<grid, THREADS, shmem>>>(nodes, edges, mask, W_in, b_in, W_gp, b_gp,
                                           Wq, Wk, Wv, Wo, ln1g, ln1b, ln2g, ln2b,
                                           W1, b1, W2, b2, outp, B);
}

// round 2
// speedup vs baseline: 1.1292x; 1.1292x over previous
#include <cuda_runtime.h>
#include <cstdint>

#define THREADS 128
#define LD      68          // row stride (floats) of activation buffers (bank-skewed)
#define NR      56          // padded rows per CTA (2 batches x 28)
#define BSTRIDE 28          // row offset of batch 1 within CTA

// SMEM working set per CTA
struct SM {
    float x[NR * LD];       // residual stream
    float h[NR * LD];       // LN output / attention output
    float q[NR * LD];       // Q (reused as FFN tmp)
    float k[NR * LD];       // K
    float v[NR * LD];       // V
    float w[28 * 128];      // staged weight, k-pair interleaved: w[kp][n] = (W[2kp][n], W[2kp+1][n])
};                          // pads n=56..63 zeroed once

__device__ __forceinline__ float fast_tanh(float x) {
    float r;
    asm("tanh.approx.f32 %0, %1;" : "=f"(r) : "f"(x));
    return r;
}
__device__ __forceinline__ float gelu_t(float x) {
    float t = fast_tanh(0.7978845608028654f * (x + 0.044715f * x * x * x));
    return 0.5f * x * (1.0f + t);
}
__device__ __forceinline__ void ffma2(unsigned long long& d, unsigned long long a, unsigned long long b) {
    asm("fma.rn.f32x2 %0, %1, %2, %0;" : "+l"(d) : "l"(a), "l"(b));
}

// Stage 56x56 weight block (gmem row stride ldw) into k-pair interleaved SMEM layout.
// dst[kp*128 + n*2 + {0,1}] = W[2kp][n], W[2kp+1][n]
__device__ __forceinline__ void stage_wp(float* __restrict__ dst, const float* __restrict__ src,
                                         int ldw, int tid) {
    #pragma unroll 1
    for (int i = tid; i < 28 * 14; i += THREADS) {
        int kp = i / 14, c4 = i % 14;
        float4 r0 = __ldg((const float4*)(src + (2 * kp)     * ldw + c4 * 4));
        float4 r1 = __ldg((const float4*)(src + (2 * kp + 1) * ldw + c4 * 4));
        float4* d = (float4*)(dst + kp * 128 + c4 * 8);
        d[0] = make_float4(r0.x, r1.x, r0.y, r1.y);
        d[1] = make_float4(r0.z, r1.z, r0.w, r1.w);
    }
}

// LayerNorm over 56 cols, thread-per-row (56 of 128 threads)
__device__ __forceinline__ void layer_norm(const float* __restrict__ X, float* __restrict__ H,
                                           const float* __restrict__ g, const float* __restrict__ b,
                                           int tid) {
    if (tid < NR) {
        const float* xr = X + tid * LD;
        float s = 0.f, ss = 0.f;
        float4 xv[14];
        #pragma unroll
        for (int j = 0; j < 14; j++) {
            xv[j] = *(const float4*)(xr + j * 4);
            s  += xv[j].x + xv[j].y + xv[j].z + xv[j].w;
            ss += xv[j].x * xv[j].x + xv[j].y * xv[j].y + xv[j].z * xv[j].z + xv[j].w * xv[j].w;
        }
        float m   = s * (1.0f / 56.0f);
        float var = ss * (1.0f / 56.0f) - m * m;
        float rs  = rsqrtf(var + 1e-5f);
        float* hr = H + tid * LD;
        #pragma unroll
        for (int j = 0; j < 14; j++) {
            float4 gv = __ldg((const float4*)(g + j * 4));
            float4 bv = __ldg((const float4*)(b + j * 4));
            float4 o;
            o.x = (xv[j].x - m) * rs * gv.x + bv.x;
            o.y = (xv[j].y - m) * rs * gv.y + bv.y;
            o.z = (xv[j].z - m) * rs * gv.z + bv.z;
            o.w = (xv[j].w - m) * rs * gv.w + bv.w;
            *(float4*)(hr + j * 4) = o;
        }
    }
}

// C[56][64] (op)= A[56][0..55] @ W[56][64]  (W in k-pair interleaved SMEM layout)
// Thread grid 8x16; tile 7 rows x 4 cols (cols tn, tn+16, tn+32, tn+48).
// Inner loop: packed fma.rn.f32x2 with k-pairs in both halves.
// MODE 0: store  1: C += acc  2: C = gelu(acc + bias[col])  3: C += acc + bias[col]
template <int MODE>
__device__ __forceinline__ void gemm_tile(const float* __restrict__ A, const float* __restrict__ Wp,
                                          float* __restrict__ C, const float* __restrict__ bias,
                                          int tid) {
    const int tm = tid >> 4;      // 0..7  -> rows tm*7 .. tm*7+6
    const int tn = tid & 15;      // 0..15 -> cols tn + 16j
    const unsigned long long* wp = (const unsigned long long*)Wp;  // [28][64] u64 pairs
    const float* Ab = A + tm * 7 * LD;

    unsigned long long acc[7][4];
    #pragma unroll
    for (int r = 0; r < 7; r++)
        #pragma unroll
        for (int j = 0; j < 4; j++) acc[r][j] = 0ULL;

    #pragma unroll 2
    for (int kq = 0; kq < 14; kq++) {        // k = 4*kq, k-pairs 2kq and 2kq+1
        unsigned long long w0[4], w1[4];
        #pragma unroll
        for (int j = 0; j < 4; j++) {
            w0[j] = wp[(2 * kq)     * 64 + tn + 16 * j];
            w1[j] = wp[(2 * kq + 1) * 64 + tn + 16 * j];
        }
        #pragma unroll
        for (int r = 0; r < 7; r++) {
            ulonglong2 av = *(const ulonglong2*)(Ab + r * LD + kq * 4);
            #pragma unroll
            for (int j = 0; j < 4; j++) ffma2(acc[r][j], av.x, w0[j]);
            #pragma unroll
            for (int j = 0; j < 4; j++) ffma2(acc[r][j], av.y, w1[j]);
        }
    }

    #pragma unroll
    for (int r = 0; r < 7; r++) {
        float* Cr = C + (tm * 7 + r) * LD;
        #pragma unroll
        for (int j = 0; j < 4; j++) {
            int col = tn + 16 * j;
            float2 p = *reinterpret_cast<float2*>(&acc[r][j]);
            float vacc = p.x + p.y;
            if (MODE == 0) {
                Cr[col] = vacc;
            } else if (MODE == 1) {
                Cr[col] += vacc;
            } else if (MODE == 2) {
                float bb = (col < 56) ? __ldg(bias + col) : 0.f;
                Cr[col] = gelu_t(vacc + bb);
            } else {
                float bb = (col < 56) ? __ldg(bias + col) : 0.f;
                Cr[col] += vacc + bb;
            }
        }
    }
}

__global__ void __launch_bounds__(THREADS)
nbody_kernel(const float* __restrict__ nodes, const float* __restrict__ edges,
             const float* __restrict__ mask,
             const float* __restrict__ W_in, const float* __restrict__ b_in,
             const float* __restrict__ W_gp, const float* __restrict__ b_gp,
             const float* __restrict__ Wq, const float* __restrict__ Wk,
             const float* __restrict__ Wv, const float* __restrict__ Wo,
             const float* __restrict__ ln1g, const float* __restrict__ ln1b,
             const float* __restrict__ ln2g, const float* __restrict__ ln2b,
             const float* __restrict__ W1, const float* __restrict__ b1,
             const float* __restrict__ W2, const float* __restrict__ b2,
             float* __restrict__ out, int Btot) {
    extern __shared__ float smem_raw[];
    SM* sm = reinterpret_cast<SM*>(smem_raw);
    const int tid = threadIdx.x;
    const int bx  = blockIdx.x;

    // ---- zero residual buffer + weight pad columns (once) ----
    #pragma unroll 1
    for (int i = tid; i < NR * LD / 4; i += THREADS)
        *(float4*)(sm->x + i * 4) = make_float4(0.f, 0.f, 0.f, 0.f);
    #pragma unroll 1
    for (int i = tid; i < 28 * 4; i += THREADS) {   // n=56..63 pads: 16 floats per kp
        int kp = i >> 2, t = i & 3;
        *(float4*)(sm->w + kp * 128 + 112 + t * 4) = make_float4(0.f, 0.f, 0.f, 0.f);
    }
    __syncthreads();

    // ---- embedding: mv_linear -> geometric product -> mv_linear ----
    if (tid < 50) {
        int g = tid / 25, s = tid % 25;
        long Bidx = (long)bx * 2 + g;
        if (Bidx < Btot) {
            const float* sp = (s < 5) ? nodes + (Bidx * 5 + s) * 24
                                      : edges + (Bidx * 20 + (s - 5)) * 24;
            float xin[24];
            #pragma unroll
            for (int i = 0; i < 24; i++) xin[i] = __ldg(sp + i);
            const int GR[8]  = {0, 1, 1, 1, 2, 2, 2, 3};
            const int POS[8] = {0, 1, 2, 4, 3, 5, 6, 7};
            float* xrow = sm->x + (g * BSTRIDE + s) * LD;
            #pragma unroll 1
            for (int n = 0; n < 7; n++) {
                float acc[8];
                #pragma unroll
                for (int i = 0; i < 8; i++) acc[i] = (i == 0) ? __ldg(b_gp + n) : 0.f;
                #pragma unroll 1
                for (int m = 0; m < 7; m++) {
                    float mv[8];
                    #pragma unroll
                    for (int i = 0; i < 8; i++) {
                        int gr = GR[i];
                        mv[i] = xin[i]      * __ldg(W_in + m * 12 + 0 + gr)
                              + xin[8 + i]  * __ldg(W_in + m * 12 + 4 + gr)
                              + xin[16 + i] * __ldg(W_in + m * 12 + 8 + gr);
                    }
                    mv[0] += __ldg(b_in + m);
                    float gp[8];
                    #pragma unroll
                    for (int j = 0; j < 8; j++) gp[j] = 0.f;
                    #pragma unroll
                    for (int a = 0; a < 8; a++) {
                        #pragma unroll
                        for (int bb = 0; bb < 8; bb++) {
                            int sc = 0;
                            #pragma unroll
                            for (int t = a >> 1; t; t >>= 1) sc += __popc(t & bb);
                            float sg = (sc & 1) ? -1.f : 1.f;
                            gp[POS[a ^ bb]] += sg * mv[POS[a]] * mv[POS[bb]];
                        }
                    }
                    #pragma unroll
                    for (int i = 0; i < 8; i++) {
                        int gr = GR[i];
                        acc[i] += mv[i] * __ldg(W_gp + n * 56 + m * 4 + gr)
                                + gp[i] * __ldg(W_gp + n * 56 + (m + 7) * 4 + gr);
                    }
                }
                #pragma unroll
                for (int i = 0; i < 8; i++) xrow[n * 8 + i] = acc[i];
            }
        }
    }
    __syncthreads();

    // ---- 4 transformer layers, fully in SMEM ----
    #pragma unroll 1
    for (int l = 0; l < 4; l++) {
        layer_norm(sm->x, sm->h, ln1g + l * 56, ln1b + l * 56, tid);
        __syncthreads();

        stage_wp(sm->w, Wq + l * 3136, 56, tid); __syncthreads();
        gemm_tile<0>(sm->h, sm->w, sm->q, nullptr, tid); __syncthreads();
        stage_wp(sm->w, Wk + l * 3136, 56, tid); __syncthreads();
        gemm_tile<0>(sm->h, sm->w, sm->k, nullptr, tid); __syncthreads();
        stage_wp(sm->w, Wv + l * 3136, 56, tid); __syncthreads();
        gemm_tile<0>(sm->h, sm->w, sm->v, nullptr, tid); __syncthreads();

        // attention: item = (batch g, head hh, query s); writes o into sm->h
        #pragma unroll 1
        for (int it = tid; it < 400; it += THREADS) {
            int g  = it / 200;
            int r  = it % 200;
            int hh = r / 25;
            int s  = r % 25;
            long Bidx = (long)bx * 2 + g;
            int rq = (g * BSTRIDE + s) * LD + hh * 7;
            float qv[7];
            #pragma unroll
            for (int d = 0; d < 7; d++) qv[d] = sm->q[rq + d];
            const float* mrow = mask + (Bidx * 25 + s) * 25;
            float sc[25];
            float mx = -1e30f;
            #pragma unroll
            for (int ki = 0; ki < 25; ki++) {
                const float* kp = sm->k + (g * BSTRIDE + ki) * LD + hh * 7;
                float dot = 0.f;
                #pragma unroll
                for (int d = 0; d < 7; d++) dot += qv[d] * kp[d];
                float msk = (Bidx < Btot) ? __ldg(mrow + ki) : 0.f;
                sc[ki] = dot * 0.3779644730092272f + msk;  // 1/sqrt(7)
                mx = fmaxf(mx, sc[ki]);
            }
            float sum = 0.f;
            #pragma unroll
            for (int ki = 0; ki < 25; ki++) { float e = __expf(sc[ki] - mx); sc[ki] = e; sum += e; }
            float inv = 1.0f / sum;
            float o[7];
            #pragma unroll
            for (int d = 0; d < 7; d++) o[d] = 0.f;
            #pragma unroll
            for (int ki = 0; ki < 25; ki++) {
                const float* vp = sm->v + (g * BSTRIDE + ki) * LD + hh * 7;
                float p = sc[ki];
                #pragma unroll
                for (int d = 0; d < 7; d++) o[d] += p * vp[d];
            }
            #pragma unroll
            for (int d = 0; d < 7; d++) sm->h[rq + d] = o[d] * inv;
        }
        __syncthreads();

        stage_wp(sm->w, Wo + l * 3136, 56, tid); __syncthreads();
        gemm_tile<1>(sm->h, sm->w, sm->x, nullptr, tid); __syncthreads();

        layer_norm(sm->x, sm->h, ln2g + l * 56, ln2b + l * 56, tid);
        __syncthreads();

        // FFN: x += gelu(h @ W1 + b1) @ W2 + b2, chunked 56 cols of Dff at a time
        #pragma unroll 1
        for (int c = 0; c < 4; c++) {
            stage_wp(sm->w, W1 + l * 12544 + c * 56, 224, tid); __syncthreads();
            gemm_tile<2>(sm->h, sm->w, sm->q, b1 + l * 224 + c * 56, tid); __syncthreads();
            stage_wp(sm->w, W2 + l * 12544 + c * 3136, 56, tid); __syncthreads();
            if (c == 3) gemm_tile<3>(sm->q, sm->w, sm->x, b2 + l * 56, tid);
            else        gemm_tile<1>(sm->q, sm->w, sm->x, nullptr, tid);
            __syncthreads();
        }
    }

    // ---- output: x[b, s<5, channel 1, :]  (D cols 8..15) ----
    if (tid < 80) {
        int g = tid / 40, r = tid % 40, s = r / 8, i = r % 8;
        long Bidx = (long)bx * 2 + g;
        if (Bidx < Btot) out[(Bidx * 5 + s) * 8 + i] = sm->x[(g * BSTRIDE + s) * LD + 8 + i];
    }
}

extern "C" void kernel_launch(void* const* d_in, const int* in_sizes, int n_in,
                              void* d_out, int out_size) {
    int o = (n_in >= 20) ? 4 : 3;  // index of W_in (scalar batch_size may be dropped)
    const float* nodes = (const float*)d_in[0];
    const float* edges = (const float*)d_in[1];
    const float* mask  = (const float*)d_in[2];
    const float* W_in  = (const float*)d_in[o + 0];
    const float* b_in  = (const float*)d_in[o + 1];
    const float* W_gp  = (const float*)d_in[o + 2];
    const float* b_gp  = (const float*)d_in[o + 3];
    const float* Wq    = (const float*)d_in[o + 4];
    const float* Wk    = (const float*)d_in[o + 5];
    const float* Wv    = (const float*)d_in[o + 6];
    const float* Wo    = (const float*)d_in[o + 7];
    const float* ln1g  = (const float*)d_in[o + 8];
    const float* ln1b  = (const float*)d_in[o + 9];
    const float* ln2g  = (const float*)d_in[o + 10];
    const float* ln2b  = (const float*)d_in[o + 11];
    const float* W1    = (const float*)d_in[o + 12];
    const float* b1    = (const float*)d_in[o + 13];
    const float* W2    = (const float*)d_in[o + 14];
    const float* b2    = (const float*)d_in[o + 15];
    float* outp = (float*)d_out;

    int B = in_sizes[0] / 120;      // nodes: (B*5, 3, 8)
    int grid = (B + 1) / 2;         // 2 batches per CTA
    size_t shmem = sizeof(SM);      // ~90.5 KB -> 2 CTAs/SM

    cudaFuncSetAttribute(nbody_kernel, cudaFuncAttributeMaxDynamicSharedMemorySize, (int)shmem);
    nbody_kernel<<<grid, THREADS, shmem>>>(nodes, edges, mask, W_in, b_in, W_gp, b_gp,
                                           Wq, Wk, Wv, Wo, ln1g, ln1b, ln2g, ln2b,
                                           W1, b1, W2, b2, outp, B);
}

// round 3
// speedup vs baseline: 1.1306x; 1.0013x over previous
#include <cuda_runtime.h>
#include <cstdint>

#define THREADS 128
#define LD      68          // row stride (floats) of activation buffers (bank-skewed)
#define NR      56          // padded rows per CTA (2 batches x 28)
#define BSTRIDE 28          // row offset of batch 1 within CTA

// SMEM working set per CTA
struct SM {
    float x[NR * LD];       // residual stream
    float h[NR * LD];       // LN output / attention output
    float q[NR * LD];       // Q (reused as FFN tmp)
    float k[NR * LD];       // K
    float v[NR * LD];       // V
    float w[28 * 128];      // staged weight, k-pair interleaved: w[kp][n] = (W[2kp][n], W[2kp+1][n])
};                          // pads n=56..63 zeroed once

__device__ __forceinline__ float fast_tanh(float x) {
    float r;
    asm("tanh.approx.f32 %0, %1;" : "=f"(r) : "f"(x));
    return r;
}
__device__ __forceinline__ float gelu_t(float x) {
    float t = fast_tanh(0.7978845608028654f * (x + 0.044715f * x * x * x));
    return 0.5f * x * (1.0f + t);
}
__device__ __forceinline__ void ffma2(unsigned long long& d, unsigned long long a, unsigned long long b) {
    asm("fma.rn.f32x2 %0, %1, %2, %0;" : "+l"(d) : "l"(a), "l"(b));
}

// Stage 56x56 weight block (gmem row stride ldw) into k-pair interleaved SMEM layout.
// dst[kp*128 + n*2 + {0,1}] = W[2kp][n], W[2kp+1][n]
__device__ __forceinline__ void stage_wp(float* __restrict__ dst, const float* __restrict__ src,
                                         int ldw, int tid) {
    #pragma unroll 1
    for (int i = tid; i < 28 * 14; i += THREADS) {
        int kp = i / 14, c4 = i % 14;
        float4 r0 = __ldg((const float4*)(src + (2 * kp)     * ldw + c4 * 4));
        float4 r1 = __ldg((const float4*)(src + (2 * kp + 1) * ldw + c4 * 4));
        float4* d = (float4*)(dst + kp * 128 + c4 * 8);
        d[0] = make_float4(r0.x, r1.x, r0.y, r1.y);
        d[1] = make_float4(r0.z, r1.z, r0.w, r1.w);
    }
}

// LayerNorm over 56 cols, thread-per-row (56 of 128 threads)
__device__ __forceinline__ void layer_norm(const float* __restrict__ X, float* __restrict__ H,
                                           const float* __restrict__ g, const float* __restrict__ b,
                                           int tid) {
    if (tid < NR) {
        const float* xr = X + tid * LD;
        float s = 0.f, ss = 0.f;
        float4 xv[14];
        #pragma unroll
        for (int j = 0; j < 14; j++) {
            xv[j] = *(const float4*)(xr + j * 4);
            s  += xv[j].x + xv[j].y + xv[j].z + xv[j].w;
            ss += xv[j].x * xv[j].x + xv[j].y * xv[j].y + xv[j].z * xv[j].z + xv[j].w * xv[j].w;
        }
        float m   = s * (1.0f / 56.0f);
        float var = ss * (1.0f / 56.0f) - m * m;
        float rs  = rsqrtf(var + 1e-5f);
        float* hr = H + tid * LD;
        #pragma unroll
        for (int j = 0; j < 14; j++) {
            float4 gv = __ldg((const float4*)(g + j * 4));
            float4 bv = __ldg((const float4*)(b + j * 4));
            float4 o;
            o.x = (xv[j].x - m) * rs * gv.x + bv.x;
            o.y = (xv[j].y - m) * rs * gv.y + bv.y;
            o.z = (xv[j].z - m) * rs * gv.z + bv.z;
            o.w = (xv[j].w - m) * rs * gv.w + bv.w;
            *(float4*)(hr + j * 4) = o;
        }
    }
}

// C[56][64] (op)= A[56][0..55] @ W[56][64]  (W in k-pair interleaved SMEM layout)
// Thread grid 8x16; tile 7 rows x 4 cols (cols tn, tn+16, tn+32, tn+48).
// Inner loop: packed fma.rn.f32x2 with k-pairs in both halves.
// MODE 0: store  1: C += acc  2: C = gelu(acc + bias[col])  3: C += acc + bias[col]
template <int MODE>
__device__ __forceinline__ void gemm_tile(const float* __restrict__ A, const float* __restrict__ Wp,
                                          float* __restrict__ C, const float* __restrict__ bias,
                                          int tid) {
    const int tm = tid >> 4;      // 0..7  -> rows tm*7 .. tm*7+6
    const int tn = tid & 15;      // 0..15 -> cols tn + 16j
    const unsigned long long* wp = (const unsigned long long*)Wp;  // [28][64] u64 pairs
    const float* Ab = A + tm * 7 * LD;

    unsigned long long acc[7][4];
    #pragma unroll
    for (int r = 0; r < 7; r++)
        #pragma unroll
        for (int j = 0; j < 4; j++) acc[r][j] = 0ULL;

    #pragma unroll 2
    for (int kq = 0; kq < 14; kq++) {        // k = 4*kq, k-pairs 2kq and 2kq+1
        unsigned long long w0[4], w1[4];
        #pragma unroll
        for (int j = 0; j < 4; j++) {
            w0[j] = wp[(2 * kq)     * 64 + tn + 16 * j];
            w1[j] = wp[(2 * kq + 1) * 64 + tn + 16 * j];
        }
        #pragma unroll
        for (int r = 0; r < 7; r++) {
            ulonglong2 av = *(const ulonglong2*)(Ab + r * LD + kq * 4);
            #pragma unroll
            for (int j = 0; j < 4; j++) ffma2(acc[r][j], av.x, w0[j]);
            #pragma unroll
            for (int j = 0; j < 4; j++) ffma2(acc[r][j], av.y, w1[j]);
        }
    }

    #pragma unroll
    for (int r = 0; r < 7; r++) {
        float* Cr = C + (tm * 7 + r) * LD;
        #pragma unroll
        for (int j = 0; j < 4; j++) {
            int col = tn + 16 * j;
            float2 p = *reinterpret_cast<float2*>(&acc[r][j]);
            float vacc = p.x + p.y;
            if (MODE == 0) {
                Cr[col] = vacc;
            } else if (MODE == 1) {
                Cr[col] += vacc;
            } else if (MODE == 2) {
                float bb = (col < 56) ? __ldg(bias + col) : 0.f;
                Cr[col] = gelu_t(vacc + bb);
            } else {
                float bb = (col < 56) ? __ldg(bias + col) : 0.f;
                Cr[col] += vacc + bb;
            }
        }
    }
}

__global__ void __launch_bounds__(THREADS)
nbody_kernel(const float* __restrict__ nodes, const float* __restrict__ edges,
             const float* __restrict__ mask,
             const float* __restrict__ W_in, const float* __restrict__ b_in,
             const float* __restrict__ W_gp, const float* __restrict__ b_gp,
             const float* __restrict__ Wq, const float* __restrict__ Wk,
             const float* __restrict__ Wv, const float* __restrict__ Wo,
             const float* __restrict__ ln1g, const float* __restrict__ ln1b,
             const float* __restrict__ ln2g, const float* __restrict__ ln2b,
             const float* __restrict__ W1, const float* __restrict__ b1,
             const float* __restrict__ W2, const float* __restrict__ b2,
             float* __restrict__ out, int Btot) {
    extern __shared__ float smem_raw[];
    SM* sm = reinterpret_cast<SM*>(smem_raw);
    const int tid = threadIdx.x;
    const int bx  = blockIdx.x;

    // ---- zero residual buffer + weight pad columns (once) ----
    #pragma unroll 1
    for (int i = tid; i < NR * LD / 4; i += THREADS)
        *(float4*)(sm->x + i * 4) = make_float4(0.f, 0.f, 0.f, 0.f);
    #pragma unroll 1
    for (int i = tid; i < 28 * 4; i += THREADS) {   // n=56..63 pads: 16 floats per kp
        int kp = i >> 2, t = i & 3;
        *(float4*)(sm->w + kp * 128 + 112 + t * 4) = make_float4(0.f, 0.f, 0.f, 0.f);
    }
    __syncthreads();

    // ---- embedding: mv_linear -> geometric product -> mv_linear ----
    if (tid < 50) {
        int g = tid / 25, s = tid % 25;
        long Bidx = (long)bx * 2 + g;
        if (Bidx < Btot) {
            const float* sp = (s < 5) ? nodes + (Bidx * 5 + s) * 24
                                      : edges + (Bidx * 20 + (s - 5)) * 24;
            float xin[24];
            #pragma unroll
            for (int i = 0; i < 24; i++) xin[i] = __ldg(sp + i);
            const int GR[8]  = {0, 1, 1, 1, 2, 2, 2, 3};
            const int POS[8] = {0, 1, 2, 4, 3, 5, 6, 7};
            float* xrow = sm->x + (g * BSTRIDE + s) * LD;
            #pragma unroll 1
            for (int n = 0; n < 7; n++) {
                float acc[8];
                #pragma unroll
                for (int i = 0; i < 8; i++) acc[i] = (i == 0) ? __ldg(b_gp + n) : 0.f;
                #pragma unroll 1
                for (int m = 0; m < 7; m++) {
                    float mv[8];
                    #pragma unroll
                    for (int i = 0; i < 8; i++) {
                        int gr = GR[i];
                        mv[i] = xin[i]      * __ldg(W_in + m * 12 + 0 + gr)
                              + xin[8 + i]  * __ldg(W_in + m * 12 + 4 + gr)
                              + xin[16 + i] * __ldg(W_in + m * 12 + 8 + gr);
                    }
                    mv[0] += __ldg(b_in + m);
                    float gp[8];
                    #pragma unroll
                    for (int j = 0; j < 8; j++) gp[j] = 0.f;
                    #pragma unroll
                    for (int a = 0; a < 8; a++) {
                        #pragma unroll
                        for (int bb = 0; bb < 8; bb++) {
                            int sc = 0;
                            #pragma unroll
                            for (int t = a >> 1; t; t >>= 1) sc += __popc(t & bb);
                            float sg = (sc & 1) ? -1.f : 1.f;
                            gp[POS[a ^ bb]] += sg * mv[POS[a]] * mv[POS[bb]];
                        }
                    }
                    #pragma unroll
                    for (int i = 0; i < 8; i++) {
                        int gr = GR[i];
                        acc[i] += mv[i] * __ldg(W_gp + n * 56 + m * 4 + gr)
                                + gp[i] * __ldg(W_gp + n * 56 + (m + 7) * 4 + gr);
                    }
                }
                #pragma unroll
                for (int i = 0; i < 8; i++) xrow[n * 8 + i] = acc[i];
            }
        }
    }
    __syncthreads();

    // ---- 4 transformer layers, fully in SMEM ----
    #pragma unroll 1
    for (int l = 0; l < 4; l++) {
        layer_norm(sm->x, sm->h, ln1g + l * 56, ln1b + l * 56, tid);
        __syncthreads();

        stage_wp(sm->w, Wq + l * 3136, 56, tid); __syncthreads();
        gemm_tile<0>(sm->h, sm->w, sm->q, nullptr, tid); __syncthreads();
        stage_wp(sm->w, Wk + l * 3136, 56, tid); __syncthreads();
        gemm_tile<0>(sm->h, sm->w, sm->k, nullptr, tid); __syncthreads();
        stage_wp(sm->w, Wv + l * 3136, 56, tid); __syncthreads();
        gemm_tile<0>(sm->h, sm->w, sm->v, nullptr, tid); __syncthreads();

        // attention: item = (batch g, head hh, query s); writes o into sm->h
        #pragma unroll 1
        for (int it = tid; it < 400; it += THREADS) {
            int g  = it / 200;
            int r  = it % 200;
            int hh = r / 25;
            int s  = r % 25;
            long Bidx = (long)bx * 2 + g;
            int rq = (g * BSTRIDE + s) * LD + hh * 7;
            float qv[7];
            #pragma unroll
            for (int d = 0; d < 7; d++) qv[d] = sm->q[rq + d];
            const float* mrow = mask + (Bidx * 25 + s) * 25;
            float sc[25];
            float mx = -1e30f;
            #pragma unroll
            for (int ki = 0; ki < 25; ki++) {
                const float* kp = sm->k + (g * BSTRIDE + ki) * LD + hh * 7;
                float dot = 0.f;
                #pragma unroll
                for (int d = 0; d < 7; d++) dot += qv[d] * kp[d];
                float msk = (Bidx < Btot) ? __ldg(mrow + ki) : 0.f;
                sc[ki] = dot * 0.3779644730092272f + msk;  // 1/sqrt(7)
                mx = fmaxf(mx, sc[ki]);
            }
            float sum = 0.f;
            #pragma unroll
            for (int ki = 0; ki < 25; ki++) { float e = __expf(sc[ki] - mx); sc[ki] = e; sum += e; }
            float inv = 1.0f / sum;
            float o[7];
            #pragma unroll
            for (int d = 0; d < 7; d++) o[d] = 0.f;
            #pragma unroll
            for (int ki = 0; ki < 25; ki++) {
                const float* vp = sm->v + (g * BSTRIDE + ki) * LD + hh * 7;
                float p = sc[ki];
                #pragma unroll
                for (int d = 0; d < 7; d++) o[d] += p * vp[d];
            }
            #pragma unroll
            for (int d = 0; d < 7; d++) sm->h[rq + d] = o[d] * inv;
        }
        __syncthreads();

        stage_wp(sm->w, Wo + l * 3136, 56, tid); __syncthreads();
        gemm_tile<1>(sm->h, sm->w, sm->x, nullptr, tid); __syncthreads();

        layer_norm(sm->x, sm->h, ln2g + l * 56, ln2b + l * 56, tid);
        __syncthreads();

        // FFN: x += gelu(h @ W1 + b1) @ W2 + b2, chunked 56 cols of Dff at a time
        #pragma unroll 1
        for (int c = 0; c < 4; c++) {
            stage_wp(sm->w, W1 + l * 12544 + c * 56, 224, tid); __syncthreads();
            gemm_tile<2>(sm->h, sm->w, sm->q, b1 + l * 224 + c * 56, tid); __syncthreads();
            stage_wp(sm->w, W2 + l * 12544 + c * 3136, 56, tid); __syncthreads();
            if (c == 3) gemm_tile<3>(sm->q, sm->w, sm->x, b2 + l * 56, tid);
            else        gemm_tile<1>(sm->q, sm->w, sm->x, nullptr, tid);
            __syncthreads();
        }
    }

    // ---- output: x[b, s<5, channel 1, :]  (D cols 8..15) ----
    if (tid < 80) {
        int g = tid / 40, r = tid % 40, s = r / 8, i = r % 8;
        long Bidx = (long)bx * 2 + g;
        if (Bidx < Btot) out[(Bidx * 5 + s) * 8 + i] = sm->x[(g * BSTRIDE + s) * LD + 8 + i];
    }
}

extern "C" void kernel_launch(void* const* d_in, const int* in_sizes, int n_in,
                              void* d_out, int out_size) {
    int o = (n_in >= 20) ? 4 : 3;  // index of W_in (scalar batch_size may be dropped)
    const float* nodes = (const float*)d_in[0];
    const float* edges = (const float*)d_in[1];
    const float* mask  = (const float*)d_in[2];
    const float* W_in  = (const float*)d_in[o + 0];
    const float* b_in  = (const float*)d_in[o + 1];
    const float* W_gp  = (const float*)d_in[o + 2];
    const float* b_gp  = (const float*)d_in[o + 3];
    const float* Wq    = (const float*)d_in[o + 4];
    const float* Wk    = (const float*)d_in[o + 5];
    const float* Wv    = (const float*)d_in[o + 6];
    const float* Wo    = (const float*)d_in[o + 7];
    const float* ln1g  = (const float*)d_in[o + 8];
    const float* ln1b  = (const float*)d_in[o + 9];
    const float* ln2g  = (const float*)d_in[o + 10];
    const float* ln2b  = (const float*)d_in[o + 11];
    const float* W1    = (const float*)d_in[o + 12];
    const float* b1    = (const float*)d_in[o + 13];
    const float* W2    = (const float*)d_in[o + 14];
    const float* b2    = (const float*)d_in[o + 15];
    float* outp = (float*)d_out;

    int B = in_sizes[0] / 120;      // nodes: (B*5, 3, 8)
    int grid = (B + 1) / 2;         // 2 batches per CTA
    size_t shmem = sizeof(SM);      // ~90.5 KB -> 2 CTAs/SM

    cudaFuncSetAttribute(nbody_kernel, cudaFuncAttributeMaxDynamicSharedMemorySize, (int)shmem);
    nbody_kernel<<<grid, THREADS, shmem>>>(nodes, edges, mask, W_in, b_in, W_gp, b_gp,
                                           Wq, Wk, Wv, Wo, ln1g, ln1b, ln2g, ln2b,
                                           W1, b1, W2, b2, outp, B);
}

// round 5
// speedup vs baseline: 1.2935x; 1.1441x over previous
#include <cuda_runtime.h>
#include <cuda_bf16.h>
#include <mma.h>
#include <cstdint>

using namespace nvcuda;

#define LDF 68            // f32 buffer row stride (floats)
#define LDA 72            // bf16 A/B row stride (elements)
#define XS_O 0u           // f32 residual  [128][68]
#define QS_O 34816u
#define KS_O 69632u
#define VS_O 104448u
#define AH_O 139264u      // bf16 A hi [128][72]; lo at +18432; A2 hi at +36864; A2 lo +55296
#define A2H_O 176128u
#define BB_O 212992u      // bf16 B hi [64][72] + lo (9216 each)
#define ALO 18432u
#define BLO 9216u
#define SMEMB 231424u

__device__ uint32_t g_wblob[48 * 4608];   // per stage: 2304 hi u32 + 2304 lo u32 ([64][72] bf16)

__device__ __forceinline__ float fast_tanh(float x) { float r; asm("tanh.approx.f32 %0, %1;" : "=f"(r) : "f"(x)); return r; }
__device__ __forceinline__ float gelu_t(float x) {
    float t = fast_tanh(0.7978845608028654f * (x + 0.044715f * x * x * x));
    return 0.5f * x * (1.0f + t);
}
__device__ __forceinline__ uint32_t pack_hl(float v0, float v1, uint32_t& lo) {
    __nv_bfloat16 h0 = __float2bfloat16(v0), h1 = __float2bfloat16(v1);
    __nv_bfloat16 l0 = __float2bfloat16(v0 - __bfloat162float(h0));
    __nv_bfloat16 l1 = __float2bfloat16(v1 - __bfloat162float(h1));
    lo = (uint32_t)__bfloat16_as_ushort(l0) | ((uint32_t)__bfloat16_as_ushort(l1) << 16);
    return (uint32_t)__bfloat16_as_ushort(h0) | ((uint32_t)__bfloat16_as_ushort(h1) << 16);
}

// ---- weight prep: 48 blocks; stage s = l*12 + {0:Wq,1:Wk,2:Wv,3:Wo,4..7:W1_c,8..11:W2_c} ----
__global__ void prep_weights(const float* __restrict__ Wq, const float* __restrict__ Wk,
                             const float* __restrict__ Wv, const float* __restrict__ Wo,
                             const float* __restrict__ W1, const float* __restrict__ W2) {
    int s = blockIdx.x, l = s / 12, r = s % 12;
    const float* src; int ldw = 56, coloff = 0, rowoff = 0;
    if      (r == 0) src = Wq + l * 3136;
    else if (r == 1) src = Wk + l * 3136;
    else if (r == 2) src = Wv + l * 3136;
    else if (r == 3) src = Wo + l * 3136;
    else if (r <  8) { src = W1 + l * 12544; ldw = 224; coloff = (r - 4) * 56; }
    else             { src = W2 + l * 12544; rowoff = (r - 8) * 56; }
    for (int idx = threadIdx.x; idx < 2304; idx += blockDim.x) {
        int k = idx / 36, n2 = idx % 36;
        int c0 = 2 * n2, c1 = c0 + 1;
        float v0 = 0.f, v1 = 0.f;
        if (k < 56) {
            if (c0 < 56) v0 = src[(rowoff + k) * ldw + coloff + c0];
            if (c1 < 56) v1 = src[(rowoff + k) * ldw + coloff + c1];
        }
        uint32_t lo, hi = pack_hl(v0, v1, lo);
        g_wblob[s * 4608 + idx] = hi;
        g_wblob[s * 4608 + 2304 + idx] = lo;
    }
}

// ---- register-prefetched B staging ----
struct BR { uint4 a, b, c, d, e; };
__device__ __forceinline__ void ldb(BR& br, int s, int tid) {
    const uint4* p = (const uint4*)(g_wblob + s * 4608);
    br.a = __ldg(p + tid);       br.b = __ldg(p + tid + 256);
    br.c = __ldg(p + tid + 512); br.d = __ldg(p + tid + 768);
    if (tid < 128) br.e = __ldg(p + tid + 1024);
}
__device__ __forceinline__ void stb(char* sm, const BR& br, int tid) {
    uint4* d = (uint4*)(sm + BB_O);
    d[tid] = br.a; d[tid + 256] = br.b; d[tid + 512] = br.c; d[tid + 768] = br.d;
    if (tid < 128) d[tid + 1024] = br.e;
}

// ---- GEMM: D[128][64] = A[128][64] @ B[64][64], bf16x3 split, warp = M-tile ----
__device__ __forceinline__ void gemm_w(char* sm, uint32_t aoffH, float* __restrict__ D, int warp) {
    const __nv_bfloat16* Ah = (const __nv_bfloat16*)(sm + aoffH);
    const __nv_bfloat16* Al = (const __nv_bfloat16*)(sm + aoffH + ALO);
    const __nv_bfloat16* Bh = (const __nv_bfloat16*)(sm + BB_O);
    const __nv_bfloat16* Bl = (const __nv_bfloat16*)(sm + BB_O + BLO);
    wmma::fragment<wmma::accumulator, 16, 16, 16, float> d[4];
    #pragma unroll
    for (int nt = 0; nt < 4; nt++) wmma::fill_fragment(d[nt], 0.0f);
    const int ar = warp * 16 * LDA;
    #pragma unroll
    for (int ks = 0; ks < 4; ks++) {
        wmma::fragment<wmma::matrix_a, 16, 16, 16, __nv_bfloat16, wmma::row_major> ah, al;
        wmma::load_matrix_sync(ah, Ah + ar + ks * 16, LDA);
        wmma::load_matrix_sync(al, Al + ar + ks * 16, LDA);
        #pragma unroll
        for (int nt = 0; nt < 4; nt++) {
            wmma::fragment<wmma::matrix_b, 16, 16, 16, __nv_bfloat16, wmma::row_major> bh, bl;
            wmma::load_matrix_sync(bh, Bh + ks * 16 * LDA + nt * 16, LDA);
            wmma::load_matrix_sync(bl, Bl + ks * 16 * LDA + nt * 16, LDA);
            wmma::mma_sync(d[nt], ah, bh, d[nt]);
            wmma::mma_sync(d[nt], ah, bl, d[nt]);
            wmma::mma_sync(d[nt], al, bh, d[nt]);
        }
    }
    #pragma unroll
    for (int nt = 0; nt < 4; nt++)
        wmma::store_matrix_sync(D + warp * 16 * LDF + nt * 16, d[nt], LDF, wmma::mem_row_major);
}

// ---- row -> bf16 hi/lo A operand (optional LN); 2 threads per row ----
template <bool DOLN>
__device__ __forceinline__ void row_cvt(const float* __restrict__ src, const float* __restrict__ g,
                                        const float* __restrict__ b, char* sm, uint32_t aoffH, int tid) {
    int r = tid >> 1, half = tid & 1;
    const float* xr = src + r * LDF + half * 28;
    float v[28];
    #pragma unroll
    for (int j = 0; j < 7; j++) *(float4*)(v + 4 * j) = *(const float4*)(xr + 4 * j);
    if (DOLN) {
        float s = 0.f, ss = 0.f;
        #pragma unroll
        for (int j = 0; j < 28; j++) { s += v[j]; ss += v[j] * v[j]; }
        s  += __shfl_xor_sync(0xffffffffu, s, 1);
        ss += __shfl_xor_sync(0xffffffffu, ss, 1);
        float m = s * (1.f / 56.f), rs = rsqrtf(ss * (1.f / 56.f) - m * m + 1e-5f);
        #pragma unroll
        for (int j = 0; j < 28; j++)
            v[j] = (v[j] - m) * rs * __ldg(g + half * 28 + j) + __ldg(b + half * 28 + j);
    }
    uint32_t* ah = (uint32_t*)(sm + aoffH + (r * LDA + half * 28) * 2);
    uint32_t* al = (uint32_t*)(sm + aoffH + ALO + (r * LDA + half * 28) * 2);
    #pragma unroll
    for (int j = 0; j < 14; j++) {
        uint32_t lo, hi = pack_hl(v[2 * j], v[2 * j + 1], lo);
        ah[j] = hi; al[j] = lo;
    }
}

// ---- x += D (+bias) ----
__device__ __forceinline__ void epi_add(float* __restrict__ xs, const float* __restrict__ D,
                                        const float* __restrict__ bias, int tid) {
    int r = tid >> 1, half = tid & 1;
    float* xr = xs + r * LDF + half * 28;
    const float* dr = D + r * LDF + half * 28;
    #pragma unroll
    for (int j = 0; j < 28; j++)
        xr[j] += dr[j] + (bias ? __ldg(bias + half * 28 + j) : 0.f);
}

// ---- A2 = split(gelu(D + b1c)) ----
__device__ __forceinline__ void epi_gelu(const float* __restrict__ D, const float* __restrict__ b1c,
                                         char* sm, int tid) {
    int r = tid >> 1, half = tid & 1;
    const float* dr = D + r * LDF + half * 28;
    float v[28];
    #pragma unroll
    for (int j = 0; j < 28; j++) v[j] = gelu_t(dr[j] + __ldg(b1c + half * 28 + j));
    uint32_t* ah = (uint32_t*)(sm + A2H_O + (r * LDA + half * 28) * 2);
    uint32_t* al = (uint32_t*)(sm + A2H_O + ALO + (r * LDA + half * 28) * 2);
    #pragma unroll
    for (int j = 0; j < 14; j++) {
        uint32_t lo, hi = pack_hl(v[2 * j], v[2 * j + 1], lo);
        ah[j] = hi; al[j] = lo;
    }
}

__global__ void __launch_bounds__(256, 1)
nbody_tc(const float* __restrict__ nodes, const float* __restrict__ edges,
         const float* __restrict__ mask,
         const float* __restrict__ W_in, const float* __restrict__ b_in,
         const float* __restrict__ W_gp, const float* __restrict__ b_gp,
         const float* __restrict__ ln1g, const float* __restrict__ ln1b,
         const float* __restrict__ ln2g, const float* __restrict__ ln2b,
         const float* __restrict__ b1, const float* __restrict__ b2,
         float* __restrict__ out, int Btot) {
    extern __shared__ char sm[];
    const int tid = threadIdx.x, bx = blockIdx.x, warp = tid >> 5;
    float* xs = (float*)(sm + XS_O);
    float* qs = (float*)(sm + QS_O);
    float* ks = (float*)(sm + KS_O);
    float* vs = (float*)(sm + VS_O);
    BR br;
    ldb(br, 0, tid);   // prefetch Wq of layer 0 behind init+embed

    // zero residual, zero A pad cols 56..63 for all 4 bf16 A buffers
    #pragma unroll 1
    for (int i = tid; i < 128 * LDF / 4; i += 256) ((float4*)xs)[i] = make_float4(0.f, 0.f, 0.f, 0.f);
    #pragma unroll 1
    for (int i = tid; i < 512; i += 256) {
        int buf = i >> 7, r = i & 127;
        *(uint4*)(sm + AH_O + buf * ALO + r * (LDA * 2) + 112) = make_uint4(0u, 0u, 0u, 0u);
    }

    // ---- embedding: mv_linear -> geometric product -> mv_linear ----
    if (tid < 100) {
        int g = tid / 25, s = tid % 25;
        long Bi = (long)bx * 4 + g;
        if (Bi < Btot) {
            const float* sp = (s < 5) ? nodes + (Bi * 5 + s) * 24 : edges + (Bi * 20 + (s - 5)) * 24;
            float xin[24];
            #pragma unroll
            for (int i = 0; i < 24; i++) xin[i] = __ldg(sp + i);
            const int GR[8] = {0, 1, 1, 1, 2, 2, 2, 3};
            const int POS[8] = {0, 1, 2, 4, 3, 5, 6, 7};
            float* xrow = xs + (g * 32 + s) * LDF;
            #pragma unroll 1
            for (int n = 0; n < 7; n++) {
                float acc[8];
                #pragma unroll
                for (int i = 0; i < 8; i++) acc[i] = (i == 0) ? __ldg(b_gp + n) : 0.f;
                #pragma unroll 1
                for (int m = 0; m < 7; m++) {
                    float mv[8];
                    #pragma unroll
                    for (int i = 0; i < 8; i++) {
                        int gr = GR[i];
                        mv[i] = xin[i] * __ldg(W_in + m * 12 + gr) + xin[8 + i] * __ldg(W_in + m * 12 + 4 + gr)
                              + xin[16 + i] * __ldg(W_in + m * 12 + 8 + gr);
                    }
                    mv[0] += __ldg(b_in + m);
                    float gp[8];
                    #pragma unroll
                    for (int j = 0; j < 8; j++) gp[j] = 0.f;
                    #pragma unroll
                    for (int a = 0; a < 8; a++)
                        #pragma unroll
                        for (int bb = 0; bb < 8; bb++) {
                            int sc = 0;
                            #pragma unroll
                            for (int t = a >> 1; t; t >>= 1) sc += __popc(t & bb);
                            gp[POS[a ^ bb]] += ((sc & 1) ? -1.f : 1.f) * mv[POS[a]] * mv[POS[bb]];
                        }
                    #pragma unroll
                    for (int i = 0; i < 8; i++) {
                        int gr = GR[i];
                        acc[i] += mv[i] * __ldg(W_gp + n * 56 + m * 4 + gr)
                                + gp[i] * __ldg(W_gp + n * 56 + (m + 7) * 4 + gr);
                    }
                }
                #pragma unroll
                for (int i = 0; i < 8; i++) xrow[n * 8 + i] = acc[i];
            }
        }
    }
    __syncthreads();
    stb(sm, br, tid);          // B <- Wq(l=0)
    __syncthreads();

    #pragma unroll 1
    for (int l = 0; l < 4; l++) {
        const int sbase = l * 12;
        row_cvt<true>(xs, ln1g + l * 56, ln1b + l * 56, sm, AH_O, tid);
        __syncthreads();

        // Q, K, V gemms (B holds Wq; prefetch next stage during each gemm)
        float* qkv0 = qs;
        #pragma unroll 1
        for (int i = 0; i < 3; i++) {
            ldb(br, sbase + 1 + i, tid);
            gemm_w(sm, AH_O, (i == 0) ? qs : ((i == 1) ? ks : vs), warp);
            __syncthreads();
            stb(sm, br, tid);
            __syncthreads();
        }
        (void)qkv0;

        // attention: writes o in place into qs
        #pragma unroll 1
        for (int it = tid; it < 800; it += 256) {
            int g = it / 200, r = it % 200, hh = r / 25, s = r % 25;
            long Bi = (long)bx * 4 + g;
            int rq = (g * 32 + s) * LDF + hh * 7;
            float qv[7];
            #pragma unroll
            for (int d = 0; d < 7; d++) qv[d] = qs[rq + d];
            const float* mrow = mask + (Bi * 25 + s) * 25;
            float sc[25]; float mx = -1e30f;
            #pragma unroll
            for (int ki = 0; ki < 25; ki++) {
                const float* kp = ks + (g * 32 + ki) * LDF + hh * 7;
                float dot = 0.f;
                #pragma unroll
                for (int d = 0; d < 7; d++) dot += qv[d] * kp[d];
                float msk = (Bi < Btot) ? __ldg(mrow + ki) : 0.f;
                sc[ki] = dot * 0.3779644730092272f + msk;
                mx = fmaxf(mx, sc[ki]);
            }
            float sum = 0.f;
            #pragma unroll
            for (int ki = 0; ki < 25; ki++) { float e = __expf(sc[ki] - mx); sc[ki] = e; sum += e; }
            float inv = 1.f / sum;
            float o[7];
            #pragma unroll
            for (int d = 0; d < 7; d++) o[d] = 0.f;
            #pragma unroll
            for (int ki = 0; ki < 25; ki++) {
                const float* vp = vs + (g * 32 + ki) * LDF + hh * 7;
                #pragma unroll
                for (int d = 0; d < 7; d++) o[d] += sc[ki] * vp[d];
            }
            #pragma unroll
            for (int d = 0; d < 7; d++) qs[rq + d] = o[d] * inv;
        }
        __syncthreads();

        // o @ Wo -> ks scratch; x += ks
        row_cvt<false>(qs, nullptr, nullptr, sm, AH_O, tid);
        __syncthreads();
        ldb(br, sbase + 4, tid);
        gemm_w(sm, AH_O, ks, warp);
        __syncthreads(); stb(sm, br, tid); __syncthreads();
        epi_add(xs, ks, nullptr, tid);
        __syncthreads();
        row_cvt<true>(xs, ln2g + l * 56, ln2b + l * 56, sm, AH_O, tid);
        __syncthreads();

        // FFN chunks: x += gelu(ln2 @ W1_c + b1_c) @ W2_c (+b2 at last chunk)
        #pragma unroll 1
        for (int c = 0; c < 4; c++) {
            ldb(br, sbase + 8 + c, tid);
            gemm_w(sm, AH_O, ks, warp);                  // ln2 @ W1_c
            __syncthreads(); stb(sm, br, tid); __syncthreads();
            epi_gelu(ks, b1 + l * 224 + c * 56, sm, tid);
            __syncthreads();
            int nxt = (c < 3) ? (sbase + 5 + c) : ((l < 3) ? (sbase + 12) : 0);
            ldb(br, nxt, tid);
            gemm_w(sm, A2H_O, vs, warp);                 // gelu @ W2_c
            __syncthreads(); stb(sm, br, tid); __syncthreads();
            epi_add(xs, vs, (c == 3) ? (b2 + l * 56) : nullptr, tid);
            __syncthreads();
        }
    }

    // ---- output: rows s<5 per batch, D cols 8..15 ----
    if (tid < 160) {
        int g = tid / 40, r = tid % 40, s = r / 8, i = r % 8;
        long Bi = (long)bx * 4 + g;
        if (Bi < Btot) out[(Bi * 5 + s) * 8 + i] = xs[(g * 32 + s) * LDF + 8 + i];
    }
}

extern "C" void kernel_launch(void* const* d_in, const int* in_sizes, int n_in,
                              void* d_out, int out_size) {
    int o = (n_in >= 20) ? 4 : 3;
    const float* nodes = (const float*)d_in[0];
    const float* edges = (const float*)d_in[1];
    const float* mask  = (const float*)d_in[2];
    const float* W_in  = (const float*)d_in[o + 0];
    const float* b_in  = (const float*)d_in[o + 1];
    const float* W_gp  = (const float*)d_in[o + 2];
    const float* b_gp  = (const float*)d_in[o + 3];
    const float* Wq    = (const float*)d_in[o + 4];
    const float* Wk    = (const float*)d_in[o + 5];
    const float* Wv    = (const float*)d_in[o + 6];
    const float* Wo    = (const float*)d_in[o + 7];
    const float* ln1g  = (const float*)d_in[o + 8];
    const float* ln1b  = (const float*)d_in[o + 9];
    const float* ln2g  = (const float*)d_in[o + 10];
    const float* ln2b  = (const float*)d_in[o + 11];
    const float* W1    = (const float*)d_in[o + 12];
    const float* b1    = (const float*)d_in[o + 13];
    const float* W2    = (const float*)d_in[o + 14];
    const float* b2    = (const float*)d_in[o + 15];

    int B = in_sizes[0] / 120;
    prep_weights<<<48, 256>>>(Wq, Wk, Wv, Wo, W1, W2);
    cudaFuncSetAttribute(nbody_tc, cudaFuncAttributeMaxDynamicSharedMemorySize, SMEMB);
    nbody_tc<<<(B + 3) / 4, 256, SMEMB>>>(nodes, edges, mask, W_in, b_in, W_gp, b_gp,
                                          ln1g, ln1b, ln2g, ln2b, b1, b2, (float*)d_out, B);
}

// round 6
// speedup vs baseline: 1.4393x; 1.1127x over previous
#include <cuda_runtime.h>
#include <cuda_bf16.h>
#include <mma.h>
#include <cstdint>

using namespace nvcuda;

#define LDF 68            // f32 buffer row stride (floats)
#define LDA 72            // bf16 operand row stride (elements)
#define XS_O 0u           // f32 residual [64][68]
#define QS_O 17408u       // q (head-padded cols 8h+d)
#define KS_O 34816u
#define VS_O 52224u       // also FFN W1-output scratch
#define AH_O 69632u       // bf16 A hi [64][72]
#define AL_O 78848u
#define BH_O 88064u       // bf16 B hi [64][72]
#define BL_O 97280u
#define SMEMB 106496u
#define A2H_O 17408u      // gelu A2 aliases qs/ks (free during FFN)
#define A2L_O 26624u

__device__ uint32_t g_wblob[48 * 4608];   // per stage: 2304 hi + 2304 lo u32 ([64][72] bf16)

__device__ __forceinline__ float fast_tanh(float x) { float r; asm("tanh.approx.f32 %0, %1;" : "=f"(r) : "f"(x)); return r; }
__device__ __forceinline__ float gelu_t(float x) {
    float t = fast_tanh(0.7978845608028654f * (x + 0.044715f * x * x * x));
    return 0.5f * x * (1.0f + t);
}
__device__ __forceinline__ uint32_t pack_hl(float v0, float v1, uint32_t& lo) {
    __nv_bfloat16 h0 = __float2bfloat16(v0), h1 = __float2bfloat16(v1);
    __nv_bfloat16 l0 = __float2bfloat16(v0 - __bfloat162float(h0));
    __nv_bfloat16 l1 = __float2bfloat16(v1 - __bfloat162float(h1));
    lo = (uint32_t)__bfloat16_as_ushort(l0) | ((uint32_t)__bfloat16_as_ushort(l1) << 16);
    return (uint32_t)__bfloat16_as_ushort(h0) | ((uint32_t)__bfloat16_as_ushort(h1) << 16);
}

// ---- weight prep: stage s = l*12 + {0:Wq,1:Wk,2:Wv,3:Wo,4..7:W1_c,8..11:W2_c} ----
// Wq/Wk/Wv cols permuted to head-padded layout (col 8h+d, d<7; 8h+7 zero).
// Wo rows permuted the same way (row 8h+7 zero).
__global__ void prep_weights(const float* __restrict__ Wq, const float* __restrict__ Wk,
                             const float* __restrict__ Wv, const float* __restrict__ Wo,
                             const float* __restrict__ W1, const float* __restrict__ W2) {
    int s = blockIdx.x, l = s / 12, r = s % 12;
    for (int idx = threadIdx.x; idx < 2304; idx += blockDim.x) {
        int k = idx / 36, n2 = idx % 36;
        float vv[2];
        #pragma unroll
        for (int t = 0; t < 2; t++) {
            int c = 2 * n2 + t;
            float v = 0.f;
            if (r < 3) {                       // Wq/Wk/Wv: col permute
                const float* src = (r == 0 ? Wq : (r == 1 ? Wk : Wv)) + l * 3136;
                int hd = c >> 3, di = c & 7;
                if (k < 56 && c < 64 && di < 7) v = src[k * 56 + hd * 7 + di];
            } else if (r == 3) {               // Wo: row permute
                const float* src = Wo + l * 3136;
                int hk = k >> 3, ki = k & 7;
                if (c < 56 && k < 64 && ki < 7) v = src[(hk * 7 + ki) * 56 + c];
            } else if (r < 8) {                // W1 chunk c: cols (r-4)*56..
                const float* src = W1 + l * 12544;
                if (k < 56 && c < 56) v = src[k * 224 + (r - 4) * 56 + c];
            } else {                           // W2 chunk: rows (r-8)*56..
                const float* src = W2 + l * 12544;
                if (k < 56 && c < 56) v = src[((r - 8) * 56 + k) * 56 + c];
            }
            vv[t] = v;
        }
        uint32_t lo, hi = pack_hl(vv[0], vv[1], lo);
        g_wblob[s * 4608 + idx] = hi;
        g_wblob[s * 4608 + 2304 + idx] = lo;
    }
}

// ---- register-prefetched B staging (1152 uint4 = 18432 B) ----
struct BR { uint4 a, b, c, d, e; };
__device__ __forceinline__ void ldb(BR& br, int s, int tid) {
    const uint4* p = (const uint4*)(g_wblob + s * 4608);
    br.a = __ldg(p + tid);       br.b = __ldg(p + tid + 256);
    br.c = __ldg(p + tid + 512); br.d = __ldg(p + tid + 768);
    if (tid < 128) br.e = __ldg(p + tid + 1024);
}
__device__ __forceinline__ void stb(char* sm, const BR& br, int tid) {
    uint4* d = (uint4*)(sm + BH_O);
    d[tid] = br.a; d[tid + 256] = br.b; d[tid + 512] = br.c; d[tid + 768] = br.d;
    if (tid < 128) d[tid + 1024] = br.e;
}

// ---- GEMM D[64][64] (+)= A[64][64] @ B[64][64]; warp = (mt, 2 nt); bf16x3 split ----
template <int ACC>
__device__ __forceinline__ void gemm_w(char* sm, uint32_t ahO, uint32_t alO,
                                       float* __restrict__ D, int warp) {
    const __nv_bfloat16* Ah = (const __nv_bfloat16*)(sm + ahO);
    const __nv_bfloat16* Al = (const __nv_bfloat16*)(sm + alO);
    const __nv_bfloat16* Bh = (const __nv_bfloat16*)(sm + BH_O);
    const __nv_bfloat16* Bl = (const __nv_bfloat16*)(sm + BL_O);
    const int mt = warp >> 1, nt0 = (warp & 1) * 2;
    wmma::fragment<wmma::accumulator, 16, 16, 16, float> d[2];
    #pragma unroll
    for (int j = 0; j < 2; j++) {
        if (ACC) wmma::load_matrix_sync(d[j], D + mt * 16 * LDF + (nt0 + j) * 16, LDF, wmma::mem_row_major);
        else     wmma::fill_fragment(d[j], 0.0f);
    }
    #pragma unroll
    for (int ks = 0; ks < 4; ks++) {
        wmma::fragment<wmma::matrix_a, 16, 16, 16, __nv_bfloat16, wmma::row_major> ah, al;
        wmma::load_matrix_sync(ah, Ah + mt * 16 * LDA + ks * 16, LDA);
        wmma::load_matrix_sync(al, Al + mt * 16 * LDA + ks * 16, LDA);
        #pragma unroll
        for (int j = 0; j < 2; j++) {
            wmma::fragment<wmma::matrix_b, 16, 16, 16, __nv_bfloat16, wmma::row_major> bh, bl;
            wmma::load_matrix_sync(bh, Bh + ks * 16 * LDA + (nt0 + j) * 16, LDA);
            wmma::load_matrix_sync(bl, Bl + ks * 16 * LDA + (nt0 + j) * 16, LDA);
            wmma::mma_sync(d[j], ah, bh, d[j]);
            wmma::mma_sync(d[j], ah, bl, d[j]);
            wmma::mma_sync(d[j], al, bh, d[j]);
        }
    }
    #pragma unroll
    for (int j = 0; j < 2; j++)
        wmma::store_matrix_sync(D + mt * 16 * LDF + (nt0 + j) * 16, d[j], LDF, wmma::mem_row_major);
}

// ---- LN of x -> A (cols 0..55); optionally also x += b2 (raw, pre-LN value kept) ----
template <bool ADDB>
__device__ __forceinline__ void row_cvt_ln(float* __restrict__ xs, const float* __restrict__ g,
                                           const float* __restrict__ b, const float* __restrict__ b2,
                                           char* sm, int tid) {
    if (tid >= 128) return;
    int r = tid >> 1, half = tid & 1;
    float* xr = xs + r * LDF + half * 28;
    float v[28];
    #pragma unroll
    for (int j = 0; j < 7; j++) *(float4*)(v + 4 * j) = *(const float4*)(xr + 4 * j);
    float s = 0.f, ss = 0.f;
    #pragma unroll
    for (int j = 0; j < 28; j++) { s += v[j]; ss += v[j] * v[j]; }
    s  += __shfl_xor_sync(0xffffffffu, s, 1);
    ss += __shfl_xor_sync(0xffffffffu, ss, 1);
    if (ADDB) {
        #pragma unroll
        for (int j = 0; j < 28; j++) xr[j] = v[j] + __ldg(b2 + half * 28 + j);
    }
    float m = s * (1.f / 56.f), rs = rsqrtf(ss * (1.f / 56.f) - m * m + 1e-5f);
    uint32_t* ah = (uint32_t*)(sm + AH_O + (r * LDA + half * 28) * 2);
    uint32_t* al = (uint32_t*)(sm + AL_O + (r * LDA + half * 28) * 2);
    #pragma unroll
    for (int j = 0; j < 14; j++) {
        float v0 = (v[2 * j]     - m) * rs * __ldg(g + half * 28 + 2 * j)     + __ldg(b + half * 28 + 2 * j);
        float v1 = (v[2 * j + 1] - m) * rs * __ldg(g + half * 28 + 2 * j + 1) + __ldg(b + half * 28 + 2 * j + 1);
        uint32_t lo, hi = pack_hl(v0, v1, lo);
        ah[j] = hi; al[j] = lo;
    }
}

// ---- o (head-padded 64 cols) -> A ----
__device__ __forceinline__ void row_cvt_o(const float* __restrict__ src, char* sm, int tid) {
    if (tid >= 128) return;
    int r = tid >> 1, half = tid & 1;
    const float* xr = src + r * LDF + half * 32;
    float v[32];
    #pragma unroll
    for (int j = 0; j < 8; j++) *(float4*)(v + 4 * j) = *(const float4*)(xr + 4 * j);
    uint32_t* ah = (uint32_t*)(sm + AH_O + (r * LDA + half * 32) * 2);
    uint32_t* al = (uint32_t*)(sm + AL_O + (r * LDA + half * 32) * 2);
    #pragma unroll
    for (int j = 0; j < 16; j++) {
        uint32_t lo, hi = pack_hl(v[2 * j], v[2 * j + 1], lo);
        ah[j] = hi; al[j] = lo;
    }
}

// ---- A2 = split(gelu(vs + b1c)); zero pad cols 56..63 ----
__device__ __forceinline__ void epi_gelu(const float* __restrict__ vsrc, const float* __restrict__ b1c,
                                         char* sm, int tid) {
    if (tid >= 128) return;
    int r = tid >> 1, half = tid & 1;
    const float* dr = vsrc + r * LDF + half * 28;
    float v[28];
    #pragma unroll
    for (int j = 0; j < 28; j++) v[j] = gelu_t(dr[j] + __ldg(b1c + half * 28 + j));
    uint32_t* ah = (uint32_t*)(sm + A2H_O + (r * LDA + half * 28) * 2);
    uint32_t* al = (uint32_t*)(sm + A2L_O + (r * LDA + half * 28) * 2);
    #pragma unroll
    for (int j = 0; j < 14; j++) {
        uint32_t lo, hi = pack_hl(v[2 * j], v[2 * j + 1], lo);
        ah[j] = hi; al[j] = lo;
    }
    if (half) {   // zero K-pad cols 56..63 (A2 aliases scratch; must re-zero)
        *(uint4*)(sm + A2H_O + (r * LDA + 56) * 2) = make_uint4(0u, 0u, 0u, 0u);
        *(uint4*)(sm + A2L_O + (r * LDA + 56) * 2) = make_uint4(0u, 0u, 0u, 0u);
    }
}

__global__ void __launch_bounds__(256, 2)
nbody_tc(const float* __restrict__ nodes, const float* __restrict__ edges,
         const float* __restrict__ mask,
         const float* __restrict__ W_in, const float* __restrict__ b_in,
         const float* __restrict__ W_gp, const float* __restrict__ b_gp,
         const float* __restrict__ ln1g, const float* __restrict__ ln1b,
         const float* __restrict__ ln2g, const float* __restrict__ ln2b,
         const float* __restrict__ b1, const float* __restrict__ b2,
         float* __restrict__ out, int Btot) {
    extern __shared__ char sm[];
    const int tid = threadIdx.x, bx = blockIdx.x, warp = tid >> 5;
    float* xs = (float*)(sm + XS_O);
    float* qs = (float*)(sm + QS_O);
    float* ks = (float*)(sm + KS_O);
    float* vs = (float*)(sm + VS_O);
    BR br;
    ldb(br, 0, tid);            // prefetch Wq(l=0) behind init+embed

    // zero residual; zero A pad cols 56..63 (persistent — row_cvt never touches them)
    #pragma unroll 1
    for (int i = tid; i < 64 * LDF / 4; i += 256) ((float4*)xs)[i] = make_float4(0.f, 0.f, 0.f, 0.f);
    if (tid < 128) {
        int buf = tid >> 6, r = tid & 63;
        *(uint4*)(sm + AH_O + (uint32_t)buf * 9216u + (r * LDA + 56) * 2) = make_uint4(0u, 0u, 0u, 0u);
    }

    // ---- embedding: mv_linear -> geometric product -> mv_linear ----
    if (tid < 50) {
        int g = tid / 25, s = tid % 25;
        long Bi = (long)bx * 2 + g;
        if (Bi < Btot) {
            const float* sp = (s < 5) ? nodes + (Bi * 5 + s) * 24 : edges + (Bi * 20 + (s - 5)) * 24;
            float xin[24];
            #pragma unroll
            for (int i = 0; i < 24; i++) xin[i] = __ldg(sp + i);
            const int GR[8] = {0, 1, 1, 1, 2, 2, 2, 3};
            const int POS[8] = {0, 1, 2, 4, 3, 5, 6, 7};
            float* xrow = xs + (g * 32 + s) * LDF;
            #pragma unroll 1
            for (int n = 0; n < 7; n++) {
                float acc[8];
                #pragma unroll
                for (int i = 0; i < 8; i++) acc[i] = (i == 0) ? __ldg(b_gp + n) : 0.f;
                #pragma unroll 1
                for (int m = 0; m < 7; m++) {
                    float mv[8];
                    #pragma unroll
                    for (int i = 0; i < 8; i++) {
                        int gr = GR[i];
                        mv[i] = xin[i] * __ldg(W_in + m * 12 + gr) + xin[8 + i] * __ldg(W_in + m * 12 + 4 + gr)
                              + xin[16 + i] * __ldg(W_in + m * 12 + 8 + gr);
                    }
                    mv[0] += __ldg(b_in + m);
                    float gp[8];
                    #pragma unroll
                    for (int j = 0; j < 8; j++) gp[j] = 0.f;
                    #pragma unroll
                    for (int a = 0; a < 8; a++)
                        #pragma unroll
                        for (int bb = 0; bb < 8; bb++) {
                            int sc = 0;
                            #pragma unroll
                            for (int t = a >> 1; t; t >>= 1) sc += __popc(t & bb);
                            gp[POS[a ^ bb]] += ((sc & 1) ? -1.f : 1.f) * mv[POS[a]] * mv[POS[bb]];
                        }
                    #pragma unroll
                    for (int i = 0; i < 8; i++) {
                        int gr = GR[i];
                        acc[i] += mv[i] * __ldg(W_gp + n * 56 + m * 4 + gr)
                                + gp[i] * __ldg(W_gp + n * 56 + (m + 7) * 4 + gr);
                    }
                }
                #pragma unroll
                for (int i = 0; i < 8; i++) xrow[n * 8 + i] = acc[i];
            }
        }
    }
    __syncthreads();
    stb(sm, br, tid);   // B <- Wq(l=0)
    __syncthreads();

    #pragma unroll 1
    for (int l = 0; l < 4; l++) {
        const int sbase = l * 12;
        row_cvt_ln<false>(xs, ln1g + l * 56, ln1b + l * 56, nullptr, sm, tid);
        __syncthreads();

        // QKV gemms with prefetch of next stage
        ldb(br, sbase + 1, tid);
        gemm_w<0>(sm, AH_O, AL_O, qs, warp);
        __syncthreads(); stb(sm, br, tid); __syncthreads();
        ldb(br, sbase + 2, tid);
        gemm_w<0>(sm, AH_O, AL_O, ks, warp);
        __syncthreads(); stb(sm, br, tid); __syncthreads();
        ldb(br, sbase + 3, tid);
        gemm_w<0>(sm, AH_O, AL_O, vs, warp);
        __syncthreads(); stb(sm, br, tid); __syncthreads();

        // attention (head-padded float4 path); o written in place into qs
        #pragma unroll 1
        for (int it = tid; it < 400; it += 256) {
            int g = it / 200, r = it % 200, hh = r / 25, s = r % 25;
            long Bi = (long)bx * 2 + g;
            int rq = (g * 32 + s) * LDF + hh * 8;
            float4 q0 = *(const float4*)(qs + rq), q1 = *(const float4*)(qs + rq + 4);
            const float* mrow = mask + (Bi * 25 + s) * 25;
            float sc[25]; float mx = -1e30f;
            #pragma unroll
            for (int ki = 0; ki < 25; ki++) {
                const float* kp = ks + (g * 32 + ki) * LDF + hh * 8;
                float4 k0 = *(const float4*)(kp), k1 = *(const float4*)(kp + 4);
                float dot = q0.x * k0.x + q0.y * k0.y + q0.z * k0.z + q0.w * k0.w
                          + q1.x * k1.x + q1.y * k1.y + q1.z * k1.z + q1.w * k1.w;
                float msk = (Bi < Btot) ? __ldg(mrow + ki) : 0.f;
                sc[ki] = dot * 0.3779644730092272f + msk;
                mx = fmaxf(mx, sc[ki]);
            }
            float sum = 0.f;
            #pragma unroll
            for (int ki = 0; ki < 25; ki++) { float e = __expf(sc[ki] - mx); sc[ki] = e; sum += e; }
            float inv = 1.f / sum;
            float4 o0 = make_float4(0.f, 0.f, 0.f, 0.f), o1 = o0;
            #pragma unroll
            for (int ki = 0; ki < 25; ki++) {
                const float* vp = vs + (g * 32 + ki) * LDF + hh * 8;
                float4 v0 = *(const float4*)(vp), v1 = *(const float4*)(vp + 4);
                float p = sc[ki];
                o0.x += p * v0.x; o0.y += p * v0.y; o0.z += p * v0.z; o0.w += p * v0.w;
                o1.x += p * v1.x; o1.y += p * v1.y; o1.z += p * v1.z; o1.w += p * v1.w;
            }
            o0.x *= inv; o0.y *= inv; o0.z *= inv; o0.w *= inv;
            o1.x *= inv; o1.y *= inv; o1.z *= inv; o1.w *= inv;
            *(float4*)(qs + rq) = o0; *(float4*)(qs + rq + 4) = o1;
        }
        __syncthreads();

        row_cvt_o(qs, sm, tid);                 // o (64 padded cols) -> A
        __syncthreads();
        ldb(br, sbase + 4, tid);
        gemm_w<1>(sm, AH_O, AL_O, xs, warp);    // x += o @ Wo (fused residual)
        __syncthreads(); stb(sm, br, tid); __syncthreads();

        row_cvt_ln<true>(xs, ln2g + l * 56, ln2b + l * 56, b2 + l * 56, sm, tid);  // ln2 -> A, x += b2
        __syncthreads();

        #pragma unroll 1
        for (int c = 0; c < 4; c++) {
            ldb(br, sbase + 8 + c, tid);
            gemm_w<0>(sm, AH_O, AL_O, vs, warp);               // ln2 @ W1_c -> vs
            __syncthreads();
            stb(sm, br, tid);
            epi_gelu(vs, b1 + l * 224 + c * 56, sm, tid);      // gelu -> A2 (overlapped with stb)
            __syncthreads();
            int nxt = (c < 3) ? (sbase + 5 + c) : ((l < 3) ? (sbase + 12) : 0);
            ldb(br, nxt, tid);
            gemm_w<1>(sm, A2H_O, A2L_O, xs, warp);             // x += gelu @ W2_c
            __syncthreads(); stb(sm, br, tid); __syncthreads();
        }
    }

    // ---- output: rows s<5 per batch, D cols 8..15 ----
    if (tid < 80) {
        int g = tid / 40, r = tid % 40, s = r / 8, i = r % 8;
        long Bi = (long)bx * 2 + g;
        if (Bi < Btot) out[(Bi * 5 + s) * 8 + i] = xs[(g * 32 + s) * LDF + 8 + i];
    }
}

extern "C" void kernel_launch(void* const* d_in, const int* in_sizes, int n_in,
                              void* d_out, int out_size) {
    int o = (n_in >= 20) ? 4 : 3;
    const float* nodes = (const float*)d_in[0];
    const float* edges = (const float*)d_in[1];
    const float* mask  = (const float*)d_in[2];
    const float* W_in  = (const float*)d_in[o + 0];
    const float* b_in  = (const float*)d_in[o + 1];
    const float* W_gp  = (const float*)d_in[o + 2];
    const float* b_gp  = (const float*)d_in[o + 3];
    const float* Wq    = (const float*)d_in[o + 4];
    const float* Wk    = (const float*)d_in[o + 5];
    const float* Wv    = (const float*)d_in[o + 6];
    const float* Wo    = (const float*)d_in[o + 7];
    const float* ln1g  = (const float*)d_in[o + 8];
    const float* ln1b  = (const float*)d_in[o + 9];
    const float* ln2g  = (const float*)d_in[o + 10];
    const float* ln2b  = (const float*)d_in[o + 11];
    const float* W1    = (const float*)d_in[o + 12];
    const float* b1    = (const float*)d_in[o + 13];
    const float* W2    = (const float*)d_in[o + 14];
    const float* b2    = (const float*)d_in[o + 15];

    int B = in_sizes[0] / 120;
    prep_weights<<<48, 256>>>(Wq, Wk, Wv, Wo, W1, W2);
    cudaFuncSetAttribute(nbody_tc, cudaFuncAttributeMaxDynamicSharedMemorySize, SMEMB);
    nbody_tc<<<(B + 1) / 2, 256, SMEMB>>>(nodes, edges, mask, W_in, b_in, W_gp, b_gp,
                                          ln1g, ln1b, ln2g, ln2b, b1, b2, (float*)d_out, B);
}

// round 7
// speedup vs baseline: 1.9872x; 1.3806x over previous
#include <cuda_runtime.h>
#include <cuda_bf16.h>
#include <cstdint>

#define LDF 68            // f32 buffer row stride (floats)
#define LDA 72            // bf16 operand row stride (elements); row = 144 B
#define XS_O 0u           // f32 residual [64][68]
#define QS_O 17408u
#define KS_O 34816u
#define VS_O 52224u
#define AH_O 69632u       // bf16 A hi [64][72]
#define AL_O 78848u
#define BH_O 88064u       // bf16 B hi [64][72]
#define BL_O 97280u
#define SMEMB 106496u
#define A2H_O 17408u      // gelu A2 aliases qs/ks scratch
#define A2L_O 26624u

__device__ uint32_t g_wblob[48 * 4608];   // per stage: 2304 hi + 2304 lo u32 ([64][72] bf16)

__device__ __forceinline__ float fast_tanh(float x) { float r; asm("tanh.approx.f32 %0, %1;" : "=f"(r) : "f"(x)); return r; }
__device__ __forceinline__ float gelu_t(float x) {
    float t = fast_tanh(0.7978845608028654f * (x + 0.044715f * x * x * x));
    return 0.5f * x * (1.0f + t);
}
__device__ __forceinline__ uint32_t pack_hl(float v0, float v1, uint32_t& lo) {
    __nv_bfloat16 h0 = __float2bfloat16(v0), h1 = __float2bfloat16(v1);
    __nv_bfloat16 l0 = __float2bfloat16(v0 - __bfloat162float(h0));
    __nv_bfloat16 l1 = __float2bfloat16(v1 - __bfloat162float(h1));
    lo = (uint32_t)__bfloat16_as_ushort(l0) | ((uint32_t)__bfloat16_as_ushort(l1) << 16);
    return (uint32_t)__bfloat16_as_ushort(h0) | ((uint32_t)__bfloat16_as_ushort(h1) << 16);
}
__device__ __forceinline__ void ldmx4(uint32_t& r0, uint32_t& r1, uint32_t& r2, uint32_t& r3, uint32_t a) {
    asm volatile("ldmatrix.sync.aligned.m8n8.x4.shared.b16 {%0,%1,%2,%3}, [%4];"
        : "=r"(r0), "=r"(r1), "=r"(r2), "=r"(r3) : "r"(a));
}
__device__ __forceinline__ void ldmx4t(uint32_t& r0, uint32_t& r1, uint32_t& r2, uint32_t& r3, uint32_t a) {
    asm volatile("ldmatrix.sync.aligned.m8n8.x4.trans.shared.b16 {%0,%1,%2,%3}, [%4];"
        : "=r"(r0), "=r"(r1), "=r"(r2), "=r"(r3) : "r"(a));
}
__device__ __forceinline__ void mma16816(float (&c)[4], uint32_t a0, uint32_t a1, uint32_t a2, uint32_t a3,
                                         uint32_t b0, uint32_t b1) {
    asm volatile("mma.sync.aligned.m16n8k16.row.col.f32.bf16.bf16.f32 "
        "{%0,%1,%2,%3}, {%4,%5,%6,%7}, {%8,%9}, {%0,%1,%2,%3};"
        : "+f"(c[0]), "+f"(c[1]), "+f"(c[2]), "+f"(c[3])
        : "r"(a0), "r"(a1), "r"(a2), "r"(a3), "r"(b0), "r"(b1));
}

// ---- weight prep: stage s = l*12 + {0:Wq,1:Wk,2:Wv,3:Wo,4..7:W1_c,8..11:W2_c} ----
__global__ void prep_weights(const float* __restrict__ Wq, const float* __restrict__ Wk,
                             const float* __restrict__ Wv, const float* __restrict__ Wo,
                             const float* __restrict__ W1, const float* __restrict__ W2) {
    int s = blockIdx.x, l = s / 12, r = s % 12;
    for (int idx = threadIdx.x; idx < 2304; idx += blockDim.x) {
        int k = idx / 36, n2 = idx % 36;
        float vv[2];
        #pragma unroll
        for (int t = 0; t < 2; t++) {
            int c = 2 * n2 + t;
            float v = 0.f;
            if (r < 3) {                       // Wq/Wk/Wv: head-padded col permute
                const float* src = (r == 0 ? Wq : (r == 1 ? Wk : Wv)) + l * 3136;
                int hd = c >> 3, di = c & 7;
                if (k < 56 && c < 64 && di < 7) v = src[k * 56 + hd * 7 + di];
            } else if (r == 3) {               // Wo: head-padded row permute
                const float* src = Wo + l * 3136;
                int hk = k >> 3, ki = k & 7;
                if (c < 56 && k < 64 && ki < 7) v = src[(hk * 7 + ki) * 56 + c];
            } else if (r < 8) {
                const float* src = W1 + l * 12544;
                if (k < 56 && c < 56) v = src[k * 224 + (r - 4) * 56 + c];
            } else {
                const float* src = W2 + l * 12544;
                if (k < 56 && c < 56) v = src[((r - 8) * 56 + k) * 56 + c];
            }
            vv[t] = v;
        }
        uint32_t lo, hi = pack_hl(vv[0], vv[1], lo);
        g_wblob[s * 4608 + idx] = hi;
        g_wblob[s * 4608 + 2304 + idx] = lo;
    }
}

// ---- register-prefetched B staging ----
struct BR { uint4 a, b, c, d, e; };
__device__ __forceinline__ void ldb(BR& br, int s, int tid) {
    const uint4* p = (const uint4*)(g_wblob + s * 4608);
    br.a = __ldg(p + tid);       br.b = __ldg(p + tid + 256);
    br.c = __ldg(p + tid + 512); br.d = __ldg(p + tid + 768);
    if (tid < 128) br.e = __ldg(p + tid + 1024);
}
__device__ __forceinline__ void stb(char* sm, const BR& br, int tid) {
    uint4* d = (uint4*)(sm + BH_O);
    d[tid] = br.a; d[tid + 256] = br.b; d[tid + 512] = br.c; d[tid + 768] = br.d;
    if (tid < 128) d[tid + 1024] = br.e;
}

// ---- GEMM D[64][64] = A[64][64] @ B[64][64] via mma.sync, bf16x3 split, fused epilogue ----
// warp -> mt = warp>>1 (16 rows), nh = warp&1 (32 cols). MODE: 0 store->Dbuf, 1 Dbuf+=, 2 gelu(+bias)->A2
template <int MODE>
__device__ __forceinline__ void gemm_m(char* sm, uint32_t smb, uint32_t ahO, uint32_t alO,
                                       float* __restrict__ Dbuf, const float* __restrict__ bias, int tid) {
    const int lane = tid & 31, warp = tid >> 5;
    const int mt = warp >> 1, nh = warp & 1;
    float c[4][4];
    #pragma unroll
    for (int j = 0; j < 4; j++) { c[j][0] = c[j][1] = c[j][2] = c[j][3] = 0.f; }

    uint32_t aoff = ((uint32_t)(mt * 16 + (lane & 15)) * LDA + 8 * (lane >> 4)) * 2;
    uint32_t ahA = smb + ahO + aoff, alA = smb + alO + aoff;
    int bg = lane >> 3, bi = lane & 7;
    uint32_t boff0 = ((uint32_t)((bg & 1) * 8 + bi) * LDA + nh * 32 + (bg >> 1) * 8) * 2;
    uint32_t bhA = smb + BH_O + boff0, blA = smb + BL_O + boff0;

    #pragma unroll
    for (int ks = 0; ks < 4; ks++) {
        uint32_t kb = ks * 32;              // A: +16 cols
        uint32_t kr = ks * (16 * LDA * 2);  // B: +16 rows
        uint32_t a0, a1, a2, a3, l0, l1, l2, l3;
        ldmx4 (a0, a1, a2, a3, ahA + kb);
        ldmx4 (l0, l1, l2, l3, alA + kb);
        uint32_t bh[8], bl[8];
        ldmx4t(bh[0], bh[1], bh[2], bh[3], bhA + kr);
        ldmx4t(bh[4], bh[5], bh[6], bh[7], bhA + kr + 32);
        ldmx4t(bl[0], bl[1], bl[2], bl[3], blA + kr);
        ldmx4t(bl[4], bl[5], bl[6], bl[7], blA + kr + 32);
        #pragma unroll
        for (int j = 0; j < 4; j++) {
            mma16816(c[j], a0, a1, a2, a3, bh[2 * j], bh[2 * j + 1]);
            mma16816(c[j], a0, a1, a2, a3, bl[2 * j], bl[2 * j + 1]);
            mma16816(c[j], l0, l1, l2, l3, bh[2 * j], bh[2 * j + 1]);
        }
    }

    const int r0 = mt * 16 + (lane >> 2);
    const int cq = (lane & 3) * 2;
    #pragma unroll
    for (int j = 0; j < 4; j++) {
        int col = nh * 32 + j * 8 + cq;
        if (MODE == 0) {
            *(float2*)(Dbuf + r0 * LDF + col)       = make_float2(c[j][0], c[j][1]);
            *(float2*)(Dbuf + (r0 + 8) * LDF + col) = make_float2(c[j][2], c[j][3]);
        } else if (MODE == 1) {
            float2 p0 = *(float2*)(Dbuf + r0 * LDF + col);
            float2 p1 = *(float2*)(Dbuf + (r0 + 8) * LDF + col);
            p0.x += c[j][0]; p0.y += c[j][1]; p1.x += c[j][2]; p1.y += c[j][3];
            *(float2*)(Dbuf + r0 * LDF + col)       = p0;
            *(float2*)(Dbuf + (r0 + 8) * LDF + col) = p1;
        } else {
            uint32_t h0 = 0, lo0 = 0, h1 = 0, lo1 = 0;
            if (!(nh == 1 && j == 3)) {          // cols 56..63: zero pads, no bias OOB
                float b0 = __ldg(bias + col), b1 = __ldg(bias + col + 1);
                h0 = pack_hl(gelu_t(c[j][0] + b0), gelu_t(c[j][1] + b1), lo0);
                h1 = pack_hl(gelu_t(c[j][2] + b0), gelu_t(c[j][3] + b1), lo1);
            }
            uint32_t o0 = ((uint32_t)(r0 * LDA + col)) * 2, o1 = ((uint32_t)((r0 + 8) * LDA + col)) * 2;
            *(uint32_t*)(sm + A2H_O + o0) = h0;  *(uint32_t*)(sm + A2L_O + o0) = lo0;
            *(uint32_t*)(sm + A2H_O + o1) = h1;  *(uint32_t*)(sm + A2L_O + o1) = lo1;
        }
    }
}

// ---- LN of x -> A bf16 hi/lo; 4 threads/row; optional x += b2 (stats from pre-b2 x) ----
template <bool ADDB>
__device__ __forceinline__ void row_cvt_ln(float* __restrict__ xs, const float* __restrict__ g,
                                           const float* __restrict__ b, const float* __restrict__ b2,
                                           char* sm, int tid) {
    int r = tid >> 2, part = tid & 3;
    float* xr = xs + r * LDF + part * 14;
    float v[14];
    #pragma unroll
    for (int j = 0; j < 7; j++) *(float2*)(v + 2 * j) = *(const float2*)(xr + 2 * j);
    float s = 0.f, ss = 0.f;
    #pragma unroll
    for (int j = 0; j < 14; j++) { s += v[j]; ss += v[j] * v[j]; }
    s  += __shfl_xor_sync(0xffffffffu, s, 1);
    ss += __shfl_xor_sync(0xffffffffu, ss, 1);
    s  += __shfl_xor_sync(0xffffffffu, s, 2);
    ss += __shfl_xor_sync(0xffffffffu, ss, 2);
    if (ADDB) {
        #pragma unroll
        for (int j = 0; j < 14; j++) xr[j] = v[j] + __ldg(b2 + part * 14 + j);
    }
    float m = s * (1.f / 56.f), rs = rsqrtf(ss * (1.f / 56.f) - m * m + 1e-5f);
    uint32_t* ah = (uint32_t*)(sm + AH_O + ((uint32_t)(r * LDA + part * 14)) * 2);
    uint32_t* al = (uint32_t*)(sm + AL_O + ((uint32_t)(r * LDA + part * 14)) * 2);
    #pragma unroll
    for (int t = 0; t < 7; t++) {
        int cl = part * 14 + 2 * t;
        float v0 = (v[2 * t]     - m) * rs * __ldg(g + cl)     + __ldg(b + cl);
        float v1 = (v[2 * t + 1] - m) * rs * __ldg(g + cl + 1) + __ldg(b + cl + 1);
        uint32_t lo, hi = pack_hl(v0, v1, lo);
        ah[t] = hi; al[t] = lo;
    }
}

__global__ void __launch_bounds__(256, 2)
nbody_tc(const float* __restrict__ nodes, const float* __restrict__ edges,
         const float* __restrict__ mask,
         const float* __restrict__ W_in, const float* __restrict__ b_in,
         const float* __restrict__ W_gp, const float* __restrict__ b_gp,
         const float* __restrict__ ln1g, const float* __restrict__ ln1b,
         const float* __restrict__ ln2g, const float* __restrict__ ln2b,
         const float* __restrict__ b1, const float* __restrict__ b2,
         float* __restrict__ out, int Btot) {
    extern __shared__ char sm[];
    const int tid = threadIdx.x, bx = blockIdx.x;
    const uint32_t smb = (uint32_t)__cvta_generic_to_shared(sm);
    float* xs = (float*)(sm + XS_O);
    float* qs = (float*)(sm + QS_O);
    float* ks = (float*)(sm + KS_O);
    float* vs = (float*)(sm + VS_O);
    BR br;
    ldb(br, 0, tid);            // prefetch Wq(l=0)

    // zero residual; zero A K-pad cols 56..63 (hi+lo) against NaN garbage
    #pragma unroll 1
    for (int i = tid; i < 64 * LDF / 4; i += 256) ((float4*)xs)[i] = make_float4(0.f, 0.f, 0.f, 0.f);
    if (tid < 128) {
        int buf = tid >> 6, r = tid & 63;
        *(uint4*)(sm + AH_O + (uint32_t)buf * (AL_O - AH_O) + ((uint32_t)(r * LDA + 56)) * 2) = make_uint4(0u, 0u, 0u, 0u);
    }

    // ---- embedding ----
    if (tid < 50) {
        int g = tid / 25, s = tid % 25;
        long Bi = (long)bx * 2 + g;
        if (Bi < Btot) {
            const float* sp = (s < 5) ? nodes + (Bi * 5 + s) * 24 : edges + (Bi * 20 + (s - 5)) * 24;
            float xin[24];
            #pragma unroll
            for (int i = 0; i < 24; i++) xin[i] = __ldg(sp + i);
            const int GR[8] = {0, 1, 1, 1, 2, 2, 2, 3};
            const int POS[8] = {0, 1, 2, 4, 3, 5, 6, 7};
            float* xrow = xs + (g * 32 + s) * LDF;
            #pragma unroll 1
            for (int n = 0; n < 7; n++) {
                float acc[8];
                #pragma unroll
                for (int i = 0; i < 8; i++) acc[i] = (i == 0) ? __ldg(b_gp + n) : 0.f;
                #pragma unroll 1
                for (int m = 0; m < 7; m++) {
                    float mv[8];
                    #pragma unroll
                    for (int i = 0; i < 8; i++) {
                        int gr = GR[i];
                        mv[i] = xin[i] * __ldg(W_in + m * 12 + gr) + xin[8 + i] * __ldg(W_in + m * 12 + 4 + gr)
                              + xin[16 + i] * __ldg(W_in + m * 12 + 8 + gr);
                    }
                    mv[0] += __ldg(b_in + m);
                    float gp[8];
                    #pragma unroll
                    for (int j = 0; j < 8; j++) gp[j] = 0.f;
                    #pragma unroll
                    for (int a = 0; a < 8; a++)
                        #pragma unroll
                        for (int bb = 0; bb < 8; bb++) {
                            int sc = 0;
                            #pragma unroll
                            for (int t = a >> 1; t; t >>= 1) sc += __popc(t & bb);
                            gp[POS[a ^ bb]] += ((sc & 1) ? -1.f : 1.f) * mv[POS[a]] * mv[POS[bb]];
                        }
                    #pragma unroll
                    for (int i = 0; i < 8; i++) {
                        int gr = GR[i];
                        acc[i] += mv[i] * __ldg(W_gp + n * 56 + m * 4 + gr)
                                + gp[i] * __ldg(W_gp + n * 56 + (m + 7) * 4 + gr);
                    }
                }
                #pragma unroll
                for (int i = 0; i < 8; i++) xrow[n * 8 + i] = acc[i];
            }
        }
    }
    __syncthreads();
    stb(sm, br, tid);   // B <- Wq(l=0)
    __syncthreads();

    #pragma unroll 1
    for (int l = 0; l < 4; l++) {
        const int sbase = l * 12;
        row_cvt_ln<false>(xs, ln1g + l * 56, ln1b + l * 56, nullptr, sm, tid);
        __syncthreads();

        ldb(br, sbase + 1, tid);
        gemm_m<0>(sm, smb, AH_O, AL_O, qs, nullptr, tid);
        __syncthreads(); stb(sm, br, tid); __syncthreads();
        ldb(br, sbase + 2, tid);
        gemm_m<0>(sm, smb, AH_O, AL_O, ks, nullptr, tid);
        __syncthreads(); stb(sm, br, tid); __syncthreads();
        ldb(br, sbase + 3, tid);
        gemm_m<0>(sm, smb, AH_O, AL_O, vs, nullptr, tid);
        __syncthreads(); stb(sm, br, tid); __syncthreads();

        // attention: o packed straight into bf16 A operand (hi/lo)
        #pragma unroll 1
        for (int it = tid; it < 400; it += 256) {
            int g = it / 200, r = it % 200, hh = r / 25, s = r % 25;
            long Bi = (long)bx * 2 + g;
            int rq = (g * 32 + s) * LDF + hh * 8;
            float4 q0 = *(const float4*)(qs + rq), q1 = *(const float4*)(qs + rq + 4);
            const float* mrow = mask + (Bi * 25 + s) * 25;
            float sc[25]; float mx = -1e30f;
            #pragma unroll
            for (int ki = 0; ki < 25; ki++) {
                const float* kp = ks + (g * 32 + ki) * LDF + hh * 8;
                float4 k0 = *(const float4*)(kp), k1 = *(const float4*)(kp + 4);
                float dot = q0.x * k0.x + q0.y * k0.y + q0.z * k0.z + q0.w * k0.w
                          + q1.x * k1.x + q1.y * k1.y + q1.z * k1.z + q1.w * k1.w;
                float msk = (Bi < Btot) ? __ldg(mrow + ki) : 0.f;
                sc[ki] = dot * 0.3779644730092272f + msk;
                mx = fmaxf(mx, sc[ki]);
            }
            float sum = 0.f;
            #pragma unroll
            for (int ki = 0; ki < 25; ki++) { float e = __expf(sc[ki] - mx); sc[ki] = e; sum += e; }
            float inv = 1.f / sum;
            float4 o0 = make_float4(0.f, 0.f, 0.f, 0.f), o1 = o0;
            #pragma unroll
            for (int ki = 0; ki < 25; ki++) {
                const float* vp = vs + (g * 32 + ki) * LDF + hh * 8;
                float4 v0 = *(const float4*)(vp), v1 = *(const float4*)(vp + 4);
                float p = sc[ki];
                o0.x += p * v0.x; o0.y += p * v0.y; o0.z += p * v0.z; o0.w += p * v0.w;
                o1.x += p * v1.x; o1.y += p * v1.y; o1.z += p * v1.z; o1.w += p * v1.w;
            }
            uint32_t ob = ((uint32_t)((g * 32 + s) * LDA + hh * 8)) * 2;
            uint32_t lo, hi;
            hi = pack_hl(o0.x * inv, o0.y * inv, lo);
            *(uint32_t*)(sm + AH_O + ob)      = hi; *(uint32_t*)(sm + AL_O + ob)      = lo;
            hi = pack_hl(o0.z * inv, o0.w * inv, lo);
            *(uint32_t*)(sm + AH_O + ob + 4)  = hi; *(uint32_t*)(sm + AL_O + ob + 4)  = lo;
            hi = pack_hl(o1.x * inv, o1.y * inv, lo);
            *(uint32_t*)(sm + AH_O + ob + 8)  = hi; *(uint32_t*)(sm + AL_O + ob + 8)  = lo;
            hi = pack_hl(o1.z * inv, o1.w * inv, lo);
            *(uint32_t*)(sm + AH_O + ob + 12) = hi; *(uint32_t*)(sm + AL_O + ob + 12) = lo;
        }
        __syncthreads();

        ldb(br, sbase + 4, tid);
        gemm_m<1>(sm, smb, AH_O, AL_O, xs, nullptr, tid);   // x += o @ Wo
        __syncthreads(); stb(sm, br, tid); __syncthreads(); // B <- W1_0

        row_cvt_ln<true>(xs, ln2g + l * 56, ln2b + l * 56, b2 + l * 56, sm, tid);
        __syncthreads();

        #pragma unroll 1
        for (int c = 0; c < 4; c++) {
            ldb(br, sbase + 8 + c, tid);
            gemm_m<2>(sm, smb, AH_O, AL_O, nullptr, b1 + l * 224 + c * 56, tid);   // gelu -> A2
            __syncthreads(); stb(sm, br, tid); __syncthreads();                    // B <- W2_c
            int nxt = (c < 3) ? (sbase + 5 + c) : ((l < 3) ? (sbase + 12) : 0);
            ldb(br, nxt, tid);
            gemm_m<1>(sm, smb, A2H_O, A2L_O, xs, nullptr, tid);                    // x += gelu @ W2_c
            __syncthreads(); stb(sm, br, tid); __syncthreads();
        }
    }

    // ---- output: rows s<5 per batch, D cols 8..15 ----
    if (tid < 80) {
        int g = tid / 40, r = tid % 40, s = r / 8, i = r % 8;
        long Bi = (long)bx * 2 + g;
        if (Bi < Btot) out[(Bi * 5 + s) * 8 + i] = xs[(g * 32 + s) * LDF + 8 + i];
    }
}

extern "C" void kernel_launch(void* const* d_in, const int* in_sizes, int n_in,
                              void* d_out, int out_size) {
    int o = (n_in >= 20) ? 4 : 3;
    const float* nodes = (const float*)d_in[0];
    const float* edges = (const float*)d_in[1];
    const float* mask  = (const float*)d_in[2];
    const float* W_in  = (const float*)d_in[o + 0];
    const float* b_in  = (const float*)d_in[o + 1];
    const float* W_gp  = (const float*)d_in[o + 2];
    const float* b_gp  = (const float*)d_in[o + 3];
    const float* Wq    = (const float*)d_in[o + 4];
    const float* Wk    = (const float*)d_in[o + 5];
    const float* Wv    = (const float*)d_in[o + 6];
    const float* Wo    = (const float*)d_in[o + 7];
    const float* ln1g  = (const float*)d_in[o + 8];
    const float* ln1b  = (const float*)d_in[o + 9];
    const float* ln2g  = (const float*)d_in[o + 10];
    const float* ln2b  = (const float*)d_in[o + 11];
    const float* W1    = (const float*)d_in[o + 12];
    const float* b1    = (const float*)d_in[o + 13];
    const float* W2    = (const float*)d_in[o + 14];
    const float* b2    = (const float*)d_in[o + 15];

    int B = in_sizes[0] / 120;
    prep_weights<<<48, 256>>>(Wq, Wk, Wv, Wo, W1, W2);
    cudaFuncSetAttribute(nbody_tc, cudaFuncAttributeMaxDynamicSharedMemorySize, SMEMB);
    nbody_tc<<<(B + 1) / 2, 256, SMEMB>>>(nodes, edges, mask, W_in, b_in, W_gp, b_gp,
                                          ln1g, ln1b, ln2g, ln2b, b1, b2, (float*)d_out, B);
}